// round 14
// baseline (speedup 1.0000x reference)
#include <cuda_runtime.h>
#include <cuda_bf16.h>
#include <math.h>
#include <stdint.h>

#define Bb   2
#define Tt   2048
#define Dd   1024
#define Hh   16
#define HDd  64
#define KK   3
#define MM   16384
#define SCALE 4096.0f

// ---------------- scratch (no cudaMalloc allowed) ----------------
__device__ float g_q[Bb*Tt*Dd];
__device__ float g_k[Bb*Tt*Dd];
__device__ float g_v[Bb*Tt*Dd];
__device__ float g_att[Bb*Tt*Dd];
__device__ float g_comb[Bb*Tt*Dd];

// tf32 split scratch
__device__ float g_xhi[Bb*Tt*Dd];
__device__ float g_xlo[Bb*Tt*Dd];
__device__ float g_whi[3*Dd*Dd];
__device__ float g_wlo[3*Dd*Dd];
__device__ float g_wohi[Dd*Dd];
__device__ float g_wolo[Dd*Dd];
// pre-split normalized K (written by l2norm, consumed by flash)
__device__ float g_khi[Bb*Tt*Dd];
__device__ float g_klo[Bb*Tt*Dd];

// ================= helpers =================
__device__ __forceinline__ void split2(float v, float& hi, float& lo) {
    hi = __uint_as_float(__float_as_uint(v) & 0xFFFFE000u);
    lo = v - hi;
}
__device__ __forceinline__ float ex2(float x) {
    float y;
    asm("ex2.approx.ftz.f32 %0, %1;" : "=f"(y) : "f"(x));
    return y;
}
__device__ __forceinline__ uint32_t smem_u32(const void* p) {
    uint32_t a;
    asm("{ .reg .u64 t; cvta.to.shared.u64 t, %1; cvt.u32.u64 %0, t; }"
        : "=r"(a) : "l"(p));
    return a;
}
__device__ __forceinline__ void cp_async16(uint32_t dst, const void* src) {
    asm volatile("cp.async.ca.shared.global [%0], [%1], 16;" :: "r"(dst), "l"(src));
}
__device__ __forceinline__ void cp_commit() {
    asm volatile("cp.async.commit_group;");
}
template<int N>
__device__ __forceinline__ void cp_wait() {
    asm volatile("cp.async.wait_group %0;" :: "n"(N));
}

// ============ fused split kernel: z=0 -> x, z=1..4 -> Wq,Wk,Wv,Wo ============
__global__ __launch_bounds__(256)
void split_all_kernel(const float* __restrict__ x,
                      const float* __restrict__ Wq, const float* __restrict__ Wk,
                      const float* __restrict__ Wv, const float* __restrict__ Wo)
{
    const int z = blockIdx.z;
    const float* src;
    float *hi, *lo;
    int n4;
    if (z == 0) {
        src = x;  hi = g_xhi;  lo = g_xlo;  n4 = Bb*Tt*Dd/4;
    } else {
        src = (z == 1) ? Wq : (z == 2) ? Wk : (z == 3) ? Wv : Wo;
        hi  = (z < 4) ? (g_whi + (size_t)(z-1) * Dd * Dd) : g_wohi;
        lo  = (z < 4) ? (g_wlo + (size_t)(z-1) * Dd * Dd) : g_wolo;
        n4  = Dd*Dd/4;
    }
    int i = blockIdx.x * blockDim.x + threadIdx.x;
    for (; i < n4; i += gridDim.x * blockDim.x) {
        float4 v = ((const float4*)src)[i];
        float4 h, l;
        split2(v.x, h.x, l.x);
        split2(v.y, h.y, l.y);
        split2(v.z, h.z, l.z);
        split2(v.w, h.w, l.w);
        ((float4*)hi)[i] = h;
        ((float4*)lo)[i] = l;
    }
}

// ================= mma.sync m16n8k8 tf32 =================
__device__ __forceinline__ void mma_16n8k8(float* d, const uint32_t* a, const uint32_t* b)
{
    asm volatile(
        "mma.sync.aligned.m16n8k8.row.col.f32.tf32.tf32.f32 "
        "{%0,%1,%2,%3}, {%4,%5,%6,%7}, {%8,%9}, {%0,%1,%2,%3};"
        : "+f"(d[0]), "+f"(d[1]), "+f"(d[2]), "+f"(d[3])
        : "r"(a[0]), "r"(a[1]), "r"(a[2]), "r"(a[3]), "r"(b[0]), "r"(b[1]));
}

// ==== tf32x3 GEMM tile (128x128, K=1024, BK=16, 2-stage cp.async) ====
#define TS2    20
#define BUF2   (128*TS2)
#define STAGE2 (4*BUF2)
#define GEMM_SMEM (2*STAGE2*4)    // 81920 B

__device__ __forceinline__ void gemm_tile_mma(
    const float* __restrict__ Ahi, const float* __restrict__ Alo,
    const float* __restrict__ Bhi, const float* __restrict__ Blo,
    const float* __restrict__ bias, float* __restrict__ C, int use_alo)
{
    extern __shared__ float sm[];
    const uint32_t sbase = smem_u32(sm);

    const int tid  = threadIdx.x;
    const int lane = tid & 31;
    const int wid  = tid >> 5;
    const int warp_m = wid >> 2;
    const int warp_n = wid & 3;
    const int m0 = blockIdx.y * 128;
    const int n0 = blockIdx.x * 128;

    float acc[4][4][4];
#pragma unroll
    for (int i = 0; i < 4; i++)
#pragma unroll
        for (int j = 0; j < 4; j++)
#pragma unroll
            for (int c = 0; c < 4; c++) acc[i][j][c] = 0.0f;

    const int lr = tid >> 1;
    const int ch = (tid & 1) * 8;

    auto stage_load = [&](int k0, int s) {
        uint32_t dst = sbase + (uint32_t)(s * STAGE2 + lr * TS2 + ch) * 4;
        const float* gAh = Ahi + (size_t)(m0 + lr) * Dd + k0 + ch;
        const float* gBh = Bhi + (size_t)(n0 + lr) * Dd + k0 + ch;
        const float* gBl = Blo + (size_t)(n0 + lr) * Dd + k0 + ch;
        cp_async16(dst,                 gAh);
        cp_async16(dst + 16,            gAh + 4);
        cp_async16(dst + 2*BUF2*4,      gBh);
        cp_async16(dst + 2*BUF2*4 + 16, gBh + 4);
        cp_async16(dst + 3*BUF2*4,      gBl);
        cp_async16(dst + 3*BUF2*4 + 16, gBl + 4);
        if (use_alo) {
            const float* gAl = Alo + (size_t)(m0 + lr) * Dd + k0 + ch;
            cp_async16(dst + BUF2*4,      gAl);
            cp_async16(dst + BUF2*4 + 16, gAl + 4);
        }
    };

    stage_load(0, 0);
    cp_commit();

    const int fr = warp_m * 64 + (lane >> 2);
    const int fn = warp_n * 32 + (lane >> 2);
    const int NIT = Dd / 16;

    for (int it = 0; it < NIT; it++) {
        const int s = it & 1;
        __syncthreads();
        if (it + 1 < NIT) {
            stage_load((it + 1) * 16, s ^ 1);
            cp_commit();
            cp_wait<1>();
        } else {
            cp_wait<0>();
        }
        __syncthreads();

        const uint32_t* uAh = (const uint32_t*)(sm + s*STAGE2);
        const uint32_t* uAl = uAh + BUF2;
        const uint32_t* uBh = uAh + 2*BUF2;
        const uint32_t* uBl = uAh + 3*BUF2;

#pragma unroll
        for (int kc = 0; kc < 2; kc++) {
            const int c0 = kc * 8 + (lane & 3);
            uint32_t af[4][4], bh[4][2], bl[4][2];
#pragma unroll
            for (int mr = 0; mr < 4; mr++) {
                int base = (fr + mr*16) * TS2 + c0;
                af[mr][0] = uAh[base];
                af[mr][1] = uAh[base + 8*TS2];
                af[mr][2] = uAh[base + 4];
                af[mr][3] = uAh[base + 8*TS2 + 4];
            }
#pragma unroll
            for (int nc = 0; nc < 4; nc++) {
                int base = (fn + nc*8) * TS2 + c0;
                bh[nc][0] = uBh[base];
                bh[nc][1] = uBh[base + 4];
                bl[nc][0] = uBl[base];
                bl[nc][1] = uBl[base + 4];
            }
#pragma unroll
            for (int mr = 0; mr < 4; mr++)
#pragma unroll
                for (int nc = 0; nc < 4; nc++)
                    mma_16n8k8(acc[mr][nc], af[mr], bh[nc]);
#pragma unroll
            for (int mr = 0; mr < 4; mr++)
#pragma unroll
                for (int nc = 0; nc < 4; nc++)
                    mma_16n8k8(acc[mr][nc], af[mr], bl[nc]);
            if (use_alo) {
#pragma unroll
                for (int mr = 0; mr < 4; mr++) {
                    int base = (fr + mr*16) * TS2 + c0;
                    af[mr][0] = uAl[base];
                    af[mr][1] = uAl[base + 8*TS2];
                    af[mr][2] = uAl[base + 4];
                    af[mr][3] = uAl[base + 8*TS2 + 4];
                }
#pragma unroll
                for (int mr = 0; mr < 4; mr++)
#pragma unroll
                    for (int nc = 0; nc < 4; nc++)
                        mma_16n8k8(acc[mr][nc], af[mr], bh[nc]);
            }
        }
    }

#pragma unroll
    for (int mr = 0; mr < 4; mr++) {
        int row = m0 + warp_m*64 + mr*16 + (lane >> 2);
#pragma unroll
        for (int nc = 0; nc < 4; nc++) {
            int col = n0 + warp_n*32 + nc*8 + (lane & 3)*2;
            float b0 = bias[col], b1 = bias[col+1];
            float2 v0 = make_float2(acc[mr][nc][0] + b0, acc[mr][nc][1] + b1);
            float2 v1 = make_float2(acc[mr][nc][2] + b0, acc[mr][nc][3] + b1);
            *(float2*)(C + (size_t)row * Dd + col)       = v0;
            *(float2*)(C + (size_t)(row+8) * Dd + col)   = v1;
        }
    }
}

__global__ __launch_bounds__(256, 2)
void gemm_qkv_kernel(const float* __restrict__ bq, const float* __restrict__ bk,
                     const float* __restrict__ bv)
{
    const int z = blockIdx.z;
    const float* Bhi = g_whi + (size_t)z * Dd * Dd;
    const float* Blo = g_wlo + (size_t)z * Dd * Dd;
    const float* bias = (z == 0) ? bq : (z == 1) ? bk : bv;
    float* C = (z == 0) ? g_q : (z == 1) ? g_k : g_v;
    gemm_tile_mma(g_xhi, g_xlo, Bhi, Blo, bias, C, 1);
}

__global__ __launch_bounds__(256, 2)
void gemm_o_kernel(const float* __restrict__ bo, float* __restrict__ out)
{
    gemm_tile_mma(g_comb, g_comb, g_wohi, g_wolo, bo, out, 0);
}

// ------- row-wise L2 normalization; K rows also pre-split to hi/lo -------
__global__ __launch_bounds__(256)
void l2norm_kernel()
{
    const int isK = blockIdx.y;
    float* buf = isK ? g_k : g_q;
    float* row = buf + (size_t)blockIdx.x * Dd;
    const int tid = threadIdx.x;

    float4 v = *(float4*)(row + tid * 4);
    float s = v.x*v.x + v.y*v.y + v.z*v.z + v.w*v.w;
#pragma unroll
    for (int o = 16; o; o >>= 1) s += __shfl_xor_sync(0xffffffffu, s, o);

    __shared__ float ws[8];
    if ((tid & 31) == 0) ws[tid >> 5] = s;
    __syncthreads();
    float tot = 0.0f;
#pragma unroll
    for (int w = 0; w < 8; w++) tot += ws[w];

    float r = 1.0f / fmaxf(sqrtf(tot), 1e-12f);
    v.x *= r; v.y *= r; v.z *= r; v.w *= r;
    if (isK) {
        float4 h, l;
        split2(v.x, h.x, l.x);
        split2(v.y, h.y, l.y);
        split2(v.z, h.z, l.z);
        split2(v.w, h.w, l.w);
        *(float4*)(g_khi + (size_t)blockIdx.x * Dd + tid * 4) = h;
        *(float4*)(g_klo + (size_t)blockIdx.x * Dd + tid * 4) = l;
    } else {
        *(float4*)(row + tid * 4) = v;
    }
}

// ============ tensor-core causal flash attention v6 (tf32x3) ============
// BM=64 (4 warps x 16 rows), BN=64, 128 threads, 2 CTAs/SM.
// Q frags hi/lo in registers; K pre-split in gmem (staged hi+lo tiles);
// V raw staged, split-on-load; P via in-warp shuffle; 3-pass mma.
#define FKS 68
#define FVS 72
#define FBUF (2*64*FKS + 64*FVS)       // 13312 floats
#define FLASH_SMEM (2*FBUF*4)          // 106496 B

__global__ __launch_bounds__(128, 2)
void flash_mma_kernel()
{
    extern __shared__ float fsm[];
    const uint32_t sbase = smem_u32(fsm);

    const int qt = (int)(gridDim.x - 1) - (int)blockIdx.x;  // big tiles first
    const int b  = blockIdx.y >> 4;
    const int h  = blockIdx.y & 15;
    const int q0 = qt * 64;
    const int tid  = threadIdx.x;
    const int lane = tid & 31;
    const int wid  = tid >> 5;
    const int row  = lane >> 2;
    const int qr   = lane & 3;
    const int r0g  = q0 + wid*16 + row;
    const int r1g  = r0g + 8;

    const size_t kvbase = (size_t)b*Tt*Dd + h*HDd;

    // ---- Q fragments into registers (log2 domain, hi/lo split) ----
    const float qsc = SCALE * 1.4426950408889634f;
    uint32_t qh[8][4], ql[8][4];
    {
        const float* q0p = g_q + kvbase + (size_t)r0g*Dd;
        const float* q1p = g_q + kvbase + (size_t)r1g*Dd;
#pragma unroll
        for (int kc = 0; kc < 8; kc++) {
            int c = kc*8 + qr;
            float a0 = q0p[c]   * qsc;
            float a1 = q1p[c]   * qsc;
            float a2 = q0p[c+4] * qsc;
            float a3 = q1p[c+4] * qsc;
            float hh, ll;
            split2(a0, hh, ll); qh[kc][0] = __float_as_uint(hh); ql[kc][0] = __float_as_uint(ll);
            split2(a1, hh, ll); qh[kc][1] = __float_as_uint(hh); ql[kc][1] = __float_as_uint(ll);
            split2(a2, hh, ll); qh[kc][2] = __float_as_uint(hh); ql[kc][2] = __float_as_uint(ll);
            split2(a3, hh, ll); qh[kc][3] = __float_as_uint(hh); ql[kc][3] = __float_as_uint(ll);
        }
    }

    float m0 = -INFINITY, m1 = -INFINITY, l0 = 0.0f, l1 = 0.0f;
    float O[8][4];
#pragma unroll
    for (int na = 0; na < 8; na++)
#pragma unroll
        for (int c = 0; c < 4; c++) O[na][c] = 0.0f;

    // stage: Khi, Klo (pre-split) + raw V tile jt into buffer buf
    auto stage = [&](int jt, int buf) {
        const float* gKh = g_khi + kvbase + (size_t)jt*64*Dd;
        const float* gKl = g_klo + kvbase + (size_t)jt*64*Dd;
        const float* gV  = g_v   + kvbase + (size_t)jt*64*Dd;
        uint32_t dKh = sbase + buf*FBUF*4;
        uint32_t dKl = dKh + 64*FKS*4;
        uint32_t dV  = dKl + 64*FKS*4;
        for (int i = tid; i < 1024; i += 128) {
            int r  = i >> 4;
            int f4 = (i & 15) * 4;
            cp_async16(dKh + (r*FKS + f4)*4, gKh + (size_t)r*Dd + f4);
            cp_async16(dKl + (r*FKS + f4)*4, gKl + (size_t)r*Dd + f4);
            cp_async16(dV  + (r*FVS + f4)*4, gV  + (size_t)r*Dd + f4);
        }
    };

    stage(0, 0);
    cp_commit();

    for (int jt = 0; jt <= qt; jt++) {
        const int cur = jt & 1;
        if (jt < qt) {
            stage(jt + 1, 1 - cur);
            cp_commit();
            cp_wait<1>();
        } else {
            cp_wait<0>();
        }
        __syncthreads();

        const uint32_t* uKh = (const uint32_t*)(fsm + cur*FBUF);
        const uint32_t* uKl = uKh + 64*FKS;
        const float*    sV  = fsm + cur*FBUF + 2*64*FKS;

        // ---- S = Q K^T (tf32x3), pre-split K frags, 3-pass mma ----
        float S[8][4];
#pragma unroll
        for (int na = 0; na < 8; na++)
#pragma unroll
            for (int c = 0; c < 4; c++) S[na][c] = 0.0f;

#pragma unroll
        for (int kc = 0; kc < 8; kc++) {
            uint32_t kh[8][2], kl[8][2];
#pragma unroll
            for (int na = 0; na < 8; na++) {
                int bb = (na*8 + row)*FKS + kc*8 + qr;
                kh[na][0] = uKh[bb];
                kh[na][1] = uKh[bb + 4];
                kl[na][0] = uKl[bb];
                kl[na][1] = uKl[bb + 4];
            }
#pragma unroll
            for (int na = 0; na < 8; na++) mma_16n8k8(S[na], qh[kc], kh[na]);
#pragma unroll
            for (int na = 0; na < 8; na++) mma_16n8k8(S[na], qh[kc], kl[na]);
#pragma unroll
            for (int na = 0; na < 8; na++) mma_16n8k8(S[na], ql[kc], kh[na]);
        }

        // ---- causal mask (only the diagonal tile) ----
        if (jt == qt) {
#pragma unroll
            for (int na = 0; na < 8; na++) {
                int c0 = jt*64 + na*8 + qr*2;
                if (c0     > r0g) S[na][0] = -INFINITY;
                if (c0 + 1 > r0g) S[na][1] = -INFINITY;
                if (c0     > r1g) S[na][2] = -INFINITY;
                if (c0 + 1 > r1g) S[na][3] = -INFINITY;
            }
        }

        // ---- online softmax (base-2) ----
        float mx0 = -INFINITY, mx1 = -INFINITY;
#pragma unroll
        for (int na = 0; na < 8; na++) {
            mx0 = fmaxf(mx0, fmaxf(S[na][0], S[na][1]));
            mx1 = fmaxf(mx1, fmaxf(S[na][2], S[na][3]));
        }
        mx0 = fmaxf(mx0, __shfl_xor_sync(0xffffffffu, mx0, 1));
        mx0 = fmaxf(mx0, __shfl_xor_sync(0xffffffffu, mx0, 2));
        mx1 = fmaxf(mx1, __shfl_xor_sync(0xffffffffu, mx1, 1));
        mx1 = fmaxf(mx1, __shfl_xor_sync(0xffffffffu, mx1, 2));

        float mn0 = fmaxf(m0, mx0), mn1 = fmaxf(m1, mx1);
        float f0 = ex2(m0 - mn0),   f1 = ex2(m1 - mn1);
        m0 = mn0; m1 = mn1;
        l0 *= f0; l1 *= f1;
#pragma unroll
        for (int na = 0; na < 8; na++) {
            O[na][0] *= f0; O[na][1] *= f0;
            O[na][2] *= f1; O[na][3] *= f1;
        }

        float rs0 = 0.0f, rs1 = 0.0f;
#pragma unroll
        for (int na = 0; na < 8; na++) {
            float p0 = ex2(S[na][0] - mn0);
            float p1 = ex2(S[na][1] - mn0);
            float p2 = ex2(S[na][2] - mn1);
            float p3 = ex2(S[na][3] - mn1);
            S[na][0] = p0; S[na][1] = p1; S[na][2] = p2; S[na][3] = p3;
            rs0 += p0 + p1;
            rs1 += p2 + p3;
        }
        rs0 += __shfl_xor_sync(0xffffffffu, rs0, 1);
        rs0 += __shfl_xor_sync(0xffffffffu, rs0, 2);
        rs1 += __shfl_xor_sync(0xffffffffu, rs1, 1);
        rs1 += __shfl_xor_sync(0xffffffffu, rs1, 2);
        l0 += rs0; l1 += rs1;

        // ---- O += P V : P via shuffle; V frags hoisted; 3-pass mma ----
        const int srcA = (lane & ~3) | (qr >> 1);
        const int srcB = srcA + 2;
        const bool odd = (qr & 1);
#pragma unroll
        for (int kc = 0; kc < 8; kc++) {
            float h0v = __shfl_sync(0xffffffffu, S[kc][0], srcA);
            float h1v = __shfl_sync(0xffffffffu, S[kc][1], srcA);
            float g0v = __shfl_sync(0xffffffffu, S[kc][0], srcB);
            float g1v = __shfl_sync(0xffffffffu, S[kc][1], srcB);
            float h2v = __shfl_sync(0xffffffffu, S[kc][2], srcA);
            float h3v = __shfl_sync(0xffffffffu, S[kc][3], srcA);
            float g2v = __shfl_sync(0xffffffffu, S[kc][2], srcB);
            float g3v = __shfl_sync(0xffffffffu, S[kc][3], srcB);
            float a0 = odd ? h1v : h0v;
            float a1 = odd ? h3v : h2v;
            float a2 = odd ? g1v : g0v;
            float a3 = odd ? g3v : g2v;
            float hh, ll;
            uint32_t ph[4], pl[4];
            split2(a0, hh, ll); ph[0] = __float_as_uint(hh); pl[0] = __float_as_uint(ll);
            split2(a1, hh, ll); ph[1] = __float_as_uint(hh); pl[1] = __float_as_uint(ll);
            split2(a2, hh, ll); ph[2] = __float_as_uint(hh); pl[2] = __float_as_uint(ll);
            split2(a3, hh, ll); ph[3] = __float_as_uint(hh); pl[3] = __float_as_uint(ll);

            int vb0 = (kc*8 + qr)*FVS + row;
            uint32_t vh[8][2], vl[8][2];
#pragma unroll
            for (int na = 0; na < 8; na++) {
                float v0 = sV[vb0 + na*8];
                float v1 = sV[vb0 + 4*FVS + na*8];
                float vh0, vl0, vh1, vl1;
                split2(v0, vh0, vl0);
                split2(v1, vh1, vl1);
                vh[na][0] = __float_as_uint(vh0);
                vh[na][1] = __float_as_uint(vh1);
                vl[na][0] = __float_as_uint(vl0);
                vl[na][1] = __float_as_uint(vl1);
            }
#pragma unroll
            for (int na = 0; na < 8; na++) mma_16n8k8(O[na], ph, vh[na]);
#pragma unroll
            for (int na = 0; na < 8; na++) mma_16n8k8(O[na], ph, vl[na]);
#pragma unroll
            for (int na = 0; na < 8; na++) mma_16n8k8(O[na], pl, vh[na]);
        }
        __syncthreads();
    }

    // ---- epilogue ----
    float inv0 = 1.0f / l0, inv1 = 1.0f / l1;
#pragma unroll
    for (int na = 0; na < 8; na++) {
        int d = na*8 + qr*2;
        *(float2*)&g_att[(size_t)b*Tt*Dd + (size_t)r0g*Dd + h*HDd + d] =
            make_float2(O[na][0]*inv0, O[na][1]*inv0);
        *(float2*)&g_att[(size_t)b*Tt*Dd + (size_t)r1g*Dd + h*HDd + d] =
            make_float2(O[na][2]*inv1, O[na][3]*inv1);
    }
}

// ---------------- KNN memory attention + gate + bf16 round ----------------
__global__ __launch_bounds__(512)
void mem_combine_kernel(const float* __restrict__ mem_bank,
                        const int*   __restrict__ knn_idx,
                        const float* __restrict__ gate_bias)
{
    const int bt = blockIdx.x;
    const int b  = bt / Tt;
    const int h  = threadIdx.x >> 5;
    const int lane = threadIdx.x & 31;

    int idxs[KK];
#pragma unroll
    for (int kk = 0; kk < KK; kk++) idxs[kk] = knn_idx[bt*KK + kk];

    const float* qrow = g_q + (size_t)bt*Dd + h*HDd;
    float q0 = qrow[lane], q1 = qrow[lane + 32];

    float lg[KK];
#pragma unroll
    for (int kk = 0; kk < KK; kk++) {
        const float* mk = mem_bank + (((size_t)b*MM + idxs[kk])*2 + 0)*Dd + h*HDd;
        float d = q0 * mk[lane] + q1 * mk[lane + 32];
#pragma unroll
        for (int o = 16; o; o >>= 1) d += __shfl_xor_sync(0xffffffffu, d, o);
        lg[kk] = d * SCALE;
    }

    float mx = fmaxf(lg[0], fmaxf(lg[1], lg[2]));
    float e0 = __expf(lg[0]-mx), e1 = __expf(lg[1]-mx), e2 = __expf(lg[2]-mx);
    float inv = 1.0f / (e0 + e1 + e2);
    e0 *= inv; e1 *= inv; e2 *= inv;

    const float* mv0 = mem_bank + (((size_t)b*MM + idxs[0])*2 + 1)*Dd + h*HDd;
    const float* mv1 = mem_bank + (((size_t)b*MM + idxs[1])*2 + 1)*Dd + h*HDd;
    const float* mv2 = mem_bank + (((size_t)b*MM + idxs[2])*2 + 1)*Dd + h*HDd;

    float o0 = e0*mv0[lane]      + e1*mv1[lane]      + e2*mv2[lane];
    float o1 = e0*mv0[lane + 32] + e1*mv1[lane + 32] + e2*mv2[lane + 32];

    float g = gate_bias[h];
    const float* arow = g_att + (size_t)bt*Dd + h*HDd;
    float c0 = o0*g + arow[lane]      * (1.0f - g);
    float c1 = o1*g + arow[lane + 32] * (1.0f - g);

    float* crow = g_comb + (size_t)bt*Dd + h*HDd;
    crow[lane]      = __bfloat162float(__float2bfloat16(c0));
    crow[lane + 32] = __bfloat162float(__float2bfloat16(c1));
}

// ---------------- launch ----------------
extern "C" void kernel_launch(void* const* d_in, const int* in_sizes, int n_in,
                              void* d_out, int out_size)
{
    (void)in_sizes; (void)n_in; (void)out_size;
    const float* x    = (const float*)d_in[0];
    const float* Wq   = (const float*)d_in[1];
    const float* bq   = (const float*)d_in[2];
    const float* Wk   = (const float*)d_in[3];
    const float* bk   = (const float*)d_in[4];
    const float* Wv   = (const float*)d_in[5];
    const float* bv   = (const float*)d_in[6];
    const float* Wo   = (const float*)d_in[7];
    const float* bo   = (const float*)d_in[8];
    const float* gate = (const float*)d_in[9];
    const float* memb = (const float*)d_in[10];
    const int*   knn  = (const int*)d_in[11];
    float* out = (float*)d_out;

    const int Mrows = Bb * Tt;           // 4096

    // launch 0: all tf32 splits fused (x + 4 weight matrices)
    split_all_kernel<<<dim3(1024, 1, 5), 256>>>(x, Wq, Wk, Wv, Wo);

    cudaFuncSetAttribute(gemm_qkv_kernel,
                         cudaFuncAttributeMaxDynamicSharedMemorySize, GEMM_SMEM);
    cudaFuncSetAttribute(gemm_o_kernel,
                         cudaFuncAttributeMaxDynamicSharedMemorySize, GEMM_SMEM);

    // launch 1
    gemm_qkv_kernel<<<dim3(Dd/128, Mrows/128, 3), 256, GEMM_SMEM>>>(bq, bk, bv);

    // launch 2
    l2norm_kernel<<<dim3(Mrows, 2), 256>>>();

    // launch 3  (ncu captures this index -> flash profile next round)
    cudaFuncSetAttribute(flash_mma_kernel,
                         cudaFuncAttributeMaxDynamicSharedMemorySize, FLASH_SMEM);
    flash_mma_kernel<<<dim3(Tt/64, Bb*Hh), 128, FLASH_SMEM>>>();

    // launch 4
    mem_combine_kernel<<<Mrows, 512>>>(memb, knn, gate);

    // launch 5
    gemm_o_kernel<<<dim3(Dd/128, Mrows/128, 1), 256, GEMM_SMEM>>>(bo, out);
}

// round 15
// speedup vs baseline: 1.0196x; 1.0196x over previous
#include <cuda_runtime.h>
#include <cuda_bf16.h>
#include <math.h>
#include <stdint.h>

#define Bb   2
#define Tt   2048
#define Dd   1024
#define Hh   16
#define HDd  64
#define KK   3
#define MM   16384
#define SCALE 4096.0f

// ---------------- scratch (no cudaMalloc allowed) ----------------
__device__ float g_q[Bb*Tt*Dd];
__device__ float g_k[Bb*Tt*Dd];
__device__ float g_v[Bb*Tt*Dd];
__device__ float g_att[Bb*Tt*Dd];
__device__ float g_comb[Bb*Tt*Dd];

// tf32 split scratch
__device__ float g_xhi[Bb*Tt*Dd];
__device__ float g_xlo[Bb*Tt*Dd];
__device__ float g_whi[3*Dd*Dd];
__device__ float g_wlo[3*Dd*Dd];
__device__ float g_wohi[Dd*Dd];
__device__ float g_wolo[Dd*Dd];

// ================= helpers =================
__device__ __forceinline__ void split2(float v, float& hi, float& lo) {
    hi = __uint_as_float(__float_as_uint(v) & 0xFFFFE000u);
    lo = v - hi;
}
__device__ __forceinline__ float ex2(float x) {
    float y;
    asm("ex2.approx.ftz.f32 %0, %1;" : "=f"(y) : "f"(x));
    return y;
}
__device__ __forceinline__ uint32_t smem_u32(const void* p) {
    uint32_t a;
    asm("{ .reg .u64 t; cvta.to.shared.u64 t, %1; cvt.u32.u64 %0, t; }"
        : "=r"(a) : "l"(p));
    return a;
}
__device__ __forceinline__ void cp_async16(uint32_t dst, const void* src) {
    asm volatile("cp.async.ca.shared.global [%0], [%1], 16;" :: "r"(dst), "l"(src));
}
__device__ __forceinline__ void cp_commit() {
    asm volatile("cp.async.commit_group;");
}
template<int N>
__device__ __forceinline__ void cp_wait() {
    asm volatile("cp.async.wait_group %0;" :: "n"(N));
}

// ============ fused split kernel: z=0 -> x, z=1..4 -> Wq,Wk,Wv,Wo ============
__global__ __launch_bounds__(256)
void split_all_kernel(const float* __restrict__ x,
                      const float* __restrict__ Wq, const float* __restrict__ Wk,
                      const float* __restrict__ Wv, const float* __restrict__ Wo)
{
    const int z = blockIdx.z;
    const float* src;
    float *hi, *lo;
    int n4;
    if (z == 0) {
        src = x;  hi = g_xhi;  lo = g_xlo;  n4 = Bb*Tt*Dd/4;
    } else {
        src = (z == 1) ? Wq : (z == 2) ? Wk : (z == 3) ? Wv : Wo;
        hi  = (z < 4) ? (g_whi + (size_t)(z-1) * Dd * Dd) : g_wohi;
        lo  = (z < 4) ? (g_wlo + (size_t)(z-1) * Dd * Dd) : g_wolo;
        n4  = Dd*Dd/4;
    }
    int i = blockIdx.x * blockDim.x + threadIdx.x;
    for (; i < n4; i += gridDim.x * blockDim.x) {
        float4 v = ((const float4*)src)[i];
        float4 h, l;
        split2(v.x, h.x, l.x);
        split2(v.y, h.y, l.y);
        split2(v.z, h.z, l.z);
        split2(v.w, h.w, l.w);
        ((float4*)hi)[i] = h;
        ((float4*)lo)[i] = l;
    }
}

// ================= mma.sync m16n8k8 tf32 =================
__device__ __forceinline__ void mma_16n8k8(float* d, const uint32_t* a, const uint32_t* b)
{
    asm volatile(
        "mma.sync.aligned.m16n8k8.row.col.f32.tf32.tf32.f32 "
        "{%0,%1,%2,%3}, {%4,%5,%6,%7}, {%8,%9}, {%0,%1,%2,%3};"
        : "+f"(d[0]), "+f"(d[1]), "+f"(d[2]), "+f"(d[3])
        : "r"(a[0]), "r"(a[1]), "r"(a[2]), "r"(a[3]), "r"(b[0]), "r"(b[1]));
}

// ==== tf32x3 GEMM tile (128x128, K=1024, BK=16, 2-stage cp.async) ====
#define TS2    20
#define BUF2   (128*TS2)
#define STAGE2 (4*BUF2)
#define GEMM_SMEM (2*STAGE2*4)    // 81920 B

__device__ __forceinline__ void gemm_tile_mma(
    const float* __restrict__ Ahi, const float* __restrict__ Alo,
    const float* __restrict__ Bhi, const float* __restrict__ Blo,
    const float* __restrict__ bias, float* __restrict__ C, int use_alo)
{
    extern __shared__ float sm[];
    const uint32_t sbase = smem_u32(sm);

    const int tid  = threadIdx.x;
    const int lane = tid & 31;
    const int wid  = tid >> 5;
    const int warp_m = wid >> 2;
    const int warp_n = wid & 3;
    const int m0 = blockIdx.y * 128;
    const int n0 = blockIdx.x * 128;

    float acc[4][4][4];
#pragma unroll
    for (int i = 0; i < 4; i++)
#pragma unroll
        for (int j = 0; j < 4; j++)
#pragma unroll
            for (int c = 0; c < 4; c++) acc[i][j][c] = 0.0f;

    const int lr = tid >> 1;
    const int ch = (tid & 1) * 8;

    auto stage_load = [&](int k0, int s) {
        uint32_t dst = sbase + (uint32_t)(s * STAGE2 + lr * TS2 + ch) * 4;
        const float* gAh = Ahi + (size_t)(m0 + lr) * Dd + k0 + ch;
        const float* gBh = Bhi + (size_t)(n0 + lr) * Dd + k0 + ch;
        const float* gBl = Blo + (size_t)(n0 + lr) * Dd + k0 + ch;
        cp_async16(dst,                 gAh);
        cp_async16(dst + 16,            gAh + 4);
        cp_async16(dst + 2*BUF2*4,      gBh);
        cp_async16(dst + 2*BUF2*4 + 16, gBh + 4);
        cp_async16(dst + 3*BUF2*4,      gBl);
        cp_async16(dst + 3*BUF2*4 + 16, gBl + 4);
        if (use_alo) {
            const float* gAl = Alo + (size_t)(m0 + lr) * Dd + k0 + ch;
            cp_async16(dst + BUF2*4,      gAl);
            cp_async16(dst + BUF2*4 + 16, gAl + 4);
        }
    };

    stage_load(0, 0);
    cp_commit();

    const int fr = warp_m * 64 + (lane >> 2);
    const int fn = warp_n * 32 + (lane >> 2);
    const int NIT = Dd / 16;

    for (int it = 0; it < NIT; it++) {
        const int s = it & 1;
        __syncthreads();
        if (it + 1 < NIT) {
            stage_load((it + 1) * 16, s ^ 1);
            cp_commit();
            cp_wait<1>();
        } else {
            cp_wait<0>();
        }
        __syncthreads();

        const uint32_t* uAh = (const uint32_t*)(sm + s*STAGE2);
        const uint32_t* uAl = uAh + BUF2;
        const uint32_t* uBh = uAh + 2*BUF2;
        const uint32_t* uBl = uAh + 3*BUF2;

#pragma unroll
        for (int kc = 0; kc < 2; kc++) {
            const int c0 = kc * 8 + (lane & 3);
            uint32_t af[4][4], bh[4][2], bl[4][2];
#pragma unroll
            for (int mr = 0; mr < 4; mr++) {
                int base = (fr + mr*16) * TS2 + c0;
                af[mr][0] = uAh[base];
                af[mr][1] = uAh[base + 8*TS2];
                af[mr][2] = uAh[base + 4];
                af[mr][3] = uAh[base + 8*TS2 + 4];
            }
#pragma unroll
            for (int nc = 0; nc < 4; nc++) {
                int base = (fn + nc*8) * TS2 + c0;
                bh[nc][0] = uBh[base];
                bh[nc][1] = uBh[base + 4];
                bl[nc][0] = uBl[base];
                bl[nc][1] = uBl[base + 4];
            }
#pragma unroll
            for (int mr = 0; mr < 4; mr++)
#pragma unroll
                for (int nc = 0; nc < 4; nc++)
                    mma_16n8k8(acc[mr][nc], af[mr], bh[nc]);
#pragma unroll
            for (int mr = 0; mr < 4; mr++)
#pragma unroll
                for (int nc = 0; nc < 4; nc++)
                    mma_16n8k8(acc[mr][nc], af[mr], bl[nc]);
            if (use_alo) {
#pragma unroll
                for (int mr = 0; mr < 4; mr++) {
                    int base = (fr + mr*16) * TS2 + c0;
                    af[mr][0] = uAl[base];
                    af[mr][1] = uAl[base + 8*TS2];
                    af[mr][2] = uAl[base + 4];
                    af[mr][3] = uAl[base + 8*TS2 + 4];
                }
#pragma unroll
                for (int mr = 0; mr < 4; mr++)
#pragma unroll
                    for (int nc = 0; nc < 4; nc++)
                        mma_16n8k8(acc[mr][nc], af[mr], bh[nc]);
            }
        }
    }

#pragma unroll
    for (int mr = 0; mr < 4; mr++) {
        int row = m0 + warp_m*64 + mr*16 + (lane >> 2);
#pragma unroll
        for (int nc = 0; nc < 4; nc++) {
            int col = n0 + warp_n*32 + nc*8 + (lane & 3)*2;
            float b0 = bias[col], b1 = bias[col+1];
            float2 v0 = make_float2(acc[mr][nc][0] + b0, acc[mr][nc][1] + b1);
            float2 v1 = make_float2(acc[mr][nc][2] + b0, acc[mr][nc][3] + b1);
            *(float2*)(C + (size_t)row * Dd + col)       = v0;
            *(float2*)(C + (size_t)(row+8) * Dd + col)   = v1;
        }
    }
}

__global__ __launch_bounds__(256, 2)
void gemm_qkv_kernel(const float* __restrict__ bq, const float* __restrict__ bk,
                     const float* __restrict__ bv)
{
    const int z = blockIdx.z;
    const float* Bhi = g_whi + (size_t)z * Dd * Dd;
    const float* Blo = g_wlo + (size_t)z * Dd * Dd;
    const float* bias = (z == 0) ? bq : (z == 1) ? bk : bv;
    float* C = (z == 0) ? g_q : (z == 1) ? g_k : g_v;
    gemm_tile_mma(g_xhi, g_xlo, Bhi, Blo, bias, C, 1);
}

__global__ __launch_bounds__(256, 2)
void gemm_o_kernel(const float* __restrict__ bo, float* __restrict__ out)
{
    gemm_tile_mma(g_comb, g_comb, g_wohi, g_wolo, bo, out, 0);
}

// ---------------- row-wise L2 normalization of g_q / g_k ----------------
__global__ __launch_bounds__(256)
void l2norm_kernel()
{
    float* buf = (blockIdx.y == 0) ? g_q : g_k;
    float* row = buf + (size_t)blockIdx.x * Dd;
    const int tid = threadIdx.x;

    float4 v = *(float4*)(row + tid * 4);
    float s = v.x*v.x + v.y*v.y + v.z*v.z + v.w*v.w;
#pragma unroll
    for (int o = 16; o; o >>= 1) s += __shfl_xor_sync(0xffffffffu, s, o);

    __shared__ float ws[8];
    if ((tid & 31) == 0) ws[tid >> 5] = s;
    __syncthreads();
    float tot = 0.0f;
#pragma unroll
    for (int w = 0; w < 8; w++) tot += ws[w];

    float r = 1.0f / fmaxf(sqrtf(tot), 1e-12f);
    v.x *= r; v.y *= r; v.z *= r; v.w *= r;
    *(float4*)(row + tid * 4) = v;
}

// ============ tensor-core causal flash attention v3 (tf32x3) ============
// Exact R13/R10 configuration (best measured): BM=64 (4 warps x 16 rows),
// BN=64, 128 threads, 2 CTAs/SM. Q frags hi/lo in registers; raw K/V staged
// via cp.async double buffer; K/V split-on-load; 3-pass mma.
#define FKS 68
#define FVS 72
#define FBUF (64*FKS + 64*FVS)
#define FLASH_SMEM (2*FBUF*4)          // 71680 B

__global__ __launch_bounds__(128, 2)
void flash_mma_kernel()
{
    extern __shared__ float fsm[];
    const uint32_t sbase = smem_u32(fsm);

    const int qt = (int)(gridDim.x - 1) - (int)blockIdx.x;  // big tiles first
    const int b  = blockIdx.y >> 4;
    const int h  = blockIdx.y & 15;
    const int q0 = qt * 64;
    const int tid  = threadIdx.x;
    const int lane = tid & 31;
    const int wid  = tid >> 5;
    const int row  = lane >> 2;
    const int qr   = lane & 3;
    const int r0g  = q0 + wid*16 + row;
    const int r1g  = r0g + 8;

    const size_t kvbase = (size_t)b*Tt*Dd + h*HDd;

    // ---- Q fragments into registers (log2 domain, hi/lo split) ----
    const float qsc = SCALE * 1.4426950408889634f;
    uint32_t qh[8][4], ql[8][4];
    {
        const float* q0p = g_q + kvbase + (size_t)r0g*Dd;
        const float* q1p = g_q + kvbase + (size_t)r1g*Dd;
#pragma unroll
        for (int kc = 0; kc < 8; kc++) {
            int c = kc*8 + qr;
            float a0 = q0p[c]   * qsc;
            float a1 = q1p[c]   * qsc;
            float a2 = q0p[c+4] * qsc;
            float a3 = q1p[c+4] * qsc;
            float hh, ll;
            split2(a0, hh, ll); qh[kc][0] = __float_as_uint(hh); ql[kc][0] = __float_as_uint(ll);
            split2(a1, hh, ll); qh[kc][1] = __float_as_uint(hh); ql[kc][1] = __float_as_uint(ll);
            split2(a2, hh, ll); qh[kc][2] = __float_as_uint(hh); ql[kc][2] = __float_as_uint(ll);
            split2(a3, hh, ll); qh[kc][3] = __float_as_uint(hh); ql[kc][3] = __float_as_uint(ll);
        }
    }

    float m0 = -INFINITY, m1 = -INFINITY, l0 = 0.0f, l1 = 0.0f;
    float O[8][4];
#pragma unroll
    for (int na = 0; na < 8; na++)
#pragma unroll
        for (int c = 0; c < 4; c++) O[na][c] = 0.0f;

    auto stage = [&](int jt, int buf) {
        const float* gK = g_k + kvbase + (size_t)jt*64*Dd;
        const float* gV = g_v + kvbase + (size_t)jt*64*Dd;
        uint32_t dK = sbase + buf*FBUF*4;
        uint32_t dV = dK + 64*FKS*4;
        for (int i = tid; i < 1024; i += 128) {
            int r  = i >> 4;
            int f4 = (i & 15) * 4;
            cp_async16(dK + (r*FKS + f4)*4, gK + (size_t)r*Dd + f4);
            cp_async16(dV + (r*FVS + f4)*4, gV + (size_t)r*Dd + f4);
        }
    };

    stage(0, 0);
    cp_commit();

    for (int jt = 0; jt <= qt; jt++) {
        const int cur = jt & 1;
        if (jt < qt) {
            stage(jt + 1, 1 - cur);
            cp_commit();
            cp_wait<1>();
        } else {
            cp_wait<0>();
        }
        __syncthreads();

        const float* sK = fsm + cur*FBUF;
        const float* sV = sK + 64*FKS;

        // ---- S = Q K^T (tf32x3), K frags hoisted, 3-pass mma ----
        float S[8][4];
#pragma unroll
        for (int na = 0; na < 8; na++)
#pragma unroll
            for (int c = 0; c < 4; c++) S[na][c] = 0.0f;

#pragma unroll
        for (int kc = 0; kc < 8; kc++) {
            uint32_t kh[8][2], kl[8][2];
#pragma unroll
            for (int na = 0; na < 8; na++) {
                int bb = (na*8 + row)*FKS + kc*8 + qr;
                float k0r = sK[bb];
                float k1r = sK[bb + 4];
                float h0, l0s, h1, l1s;
                split2(k0r, h0, l0s);
                split2(k1r, h1, l1s);
                kh[na][0] = __float_as_uint(h0);
                kh[na][1] = __float_as_uint(h1);
                kl[na][0] = __float_as_uint(l0s);
                kl[na][1] = __float_as_uint(l1s);
            }
#pragma unroll
            for (int na = 0; na < 8; na++) mma_16n8k8(S[na], qh[kc], kh[na]);
#pragma unroll
            for (int na = 0; na < 8; na++) mma_16n8k8(S[na], qh[kc], kl[na]);
#pragma unroll
            for (int na = 0; na < 8; na++) mma_16n8k8(S[na], ql[kc], kh[na]);
        }

        // ---- causal mask (only the diagonal tile) ----
        if (jt == qt) {
#pragma unroll
            for (int na = 0; na < 8; na++) {
                int c0 = jt*64 + na*8 + qr*2;
                if (c0     > r0g) S[na][0] = -INFINITY;
                if (c0 + 1 > r0g) S[na][1] = -INFINITY;
                if (c0     > r1g) S[na][2] = -INFINITY;
                if (c0 + 1 > r1g) S[na][3] = -INFINITY;
            }
        }

        // ---- online softmax (base-2) ----
        float mx0 = -INFINITY, mx1 = -INFINITY;
#pragma unroll
        for (int na = 0; na < 8; na++) {
            mx0 = fmaxf(mx0, fmaxf(S[na][0], S[na][1]));
            mx1 = fmaxf(mx1, fmaxf(S[na][2], S[na][3]));
        }
        mx0 = fmaxf(mx0, __shfl_xor_sync(0xffffffffu, mx0, 1));
        mx0 = fmaxf(mx0, __shfl_xor_sync(0xffffffffu, mx0, 2));
        mx1 = fmaxf(mx1, __shfl_xor_sync(0xffffffffu, mx1, 1));
        mx1 = fmaxf(mx1, __shfl_xor_sync(0xffffffffu, mx1, 2));

        float mn0 = fmaxf(m0, mx0), mn1 = fmaxf(m1, mx1);
        float f0 = ex2(m0 - mn0),   f1 = ex2(m1 - mn1);
        m0 = mn0; m1 = mn1;
        l0 *= f0; l1 *= f1;
#pragma unroll
        for (int na = 0; na < 8; na++) {
            O[na][0] *= f0; O[na][1] *= f0;
            O[na][2] *= f1; O[na][3] *= f1;
        }

        float rs0 = 0.0f, rs1 = 0.0f;
#pragma unroll
        for (int na = 0; na < 8; na++) {
            float p0 = ex2(S[na][0] - mn0);
            float p1 = ex2(S[na][1] - mn0);
            float p2 = ex2(S[na][2] - mn1);
            float p3 = ex2(S[na][3] - mn1);
            S[na][0] = p0; S[na][1] = p1; S[na][2] = p2; S[na][3] = p3;
            rs0 += p0 + p1;
            rs1 += p2 + p3;
        }
        rs0 += __shfl_xor_sync(0xffffffffu, rs0, 1);
        rs0 += __shfl_xor_sync(0xffffffffu, rs0, 2);
        rs1 += __shfl_xor_sync(0xffffffffu, rs1, 1);
        rs1 += __shfl_xor_sync(0xffffffffu, rs1, 2);
        l0 += rs0; l1 += rs1;

        // ---- O += P V : P via shuffle; V frags hoisted; 3-pass mma ----
        const int srcA = (lane & ~3) | (qr >> 1);
        const int srcB = srcA + 2;
        const bool odd = (qr & 1);
#pragma unroll
        for (int kc = 0; kc < 8; kc++) {
            float h0v = __shfl_sync(0xffffffffu, S[kc][0], srcA);
            float h1v = __shfl_sync(0xffffffffu, S[kc][1], srcA);
            float g0v = __shfl_sync(0xffffffffu, S[kc][0], srcB);
            float g1v = __shfl_sync(0xffffffffu, S[kc][1], srcB);
            float h2v = __shfl_sync(0xffffffffu, S[kc][2], srcA);
            float h3v = __shfl_sync(0xffffffffu, S[kc][3], srcA);
            float g2v = __shfl_sync(0xffffffffu, S[kc][2], srcB);
            float g3v = __shfl_sync(0xffffffffu, S[kc][3], srcB);
            float a0 = odd ? h1v : h0v;
            float a1 = odd ? h3v : h2v;
            float a2 = odd ? g1v : g0v;
            float a3 = odd ? g3v : g2v;
            float hh, ll;
            uint32_t ph[4], pl[4];
            split2(a0, hh, ll); ph[0] = __float_as_uint(hh); pl[0] = __float_as_uint(ll);
            split2(a1, hh, ll); ph[1] = __float_as_uint(hh); pl[1] = __float_as_uint(ll);
            split2(a2, hh, ll); ph[2] = __float_as_uint(hh); pl[2] = __float_as_uint(ll);
            split2(a3, hh, ll); ph[3] = __float_as_uint(hh); pl[3] = __float_as_uint(ll);

            int vb0 = (kc*8 + qr)*FVS + row;
            uint32_t vh[8][2], vl[8][2];
#pragma unroll
            for (int na = 0; na < 8; na++) {
                float v0 = sV[vb0 + na*8];
                float v1 = sV[vb0 + 4*FVS + na*8];
                float vh0, vl0, vh1, vl1;
                split2(v0, vh0, vl0);
                split2(v1, vh1, vl1);
                vh[na][0] = __float_as_uint(vh0);
                vh[na][1] = __float_as_uint(vh1);
                vl[na][0] = __float_as_uint(vl0);
                vl[na][1] = __float_as_uint(vl1);
            }
#pragma unroll
            for (int na = 0; na < 8; na++) mma_16n8k8(O[na], ph, vh[na]);
#pragma unroll
            for (int na = 0; na < 8; na++) mma_16n8k8(O[na], ph, vl[na]);
#pragma unroll
            for (int na = 0; na < 8; na++) mma_16n8k8(O[na], pl, vh[na]);
        }
        __syncthreads();
    }

    // ---- epilogue ----
    float inv0 = 1.0f / l0, inv1 = 1.0f / l1;
#pragma unroll
    for (int na = 0; na < 8; na++) {
        int d = na*8 + qr*2;
        *(float2*)&g_att[(size_t)b*Tt*Dd + (size_t)r0g*Dd + h*HDd + d] =
            make_float2(O[na][0]*inv0, O[na][1]*inv0);
        *(float2*)&g_att[(size_t)b*Tt*Dd + (size_t)r1g*Dd + h*HDd + d] =
            make_float2(O[na][2]*inv1, O[na][3]*inv1);
    }
}

// ---------------- KNN memory attention + gate + bf16 round ----------------
__global__ __launch_bounds__(512)
void mem_combine_kernel(const float* __restrict__ mem_bank,
                        const int*   __restrict__ knn_idx,
                        const float* __restrict__ gate_bias)
{
    const int bt = blockIdx.x;
    const int b  = bt / Tt;
    const int h  = threadIdx.x >> 5;
    const int lane = threadIdx.x & 31;

    int idxs[KK];
#pragma unroll
    for (int kk = 0; kk < KK; kk++) idxs[kk] = knn_idx[bt*KK + kk];

    const float* qrow = g_q + (size_t)bt*Dd + h*HDd;
    float q0 = qrow[lane], q1 = qrow[lane + 32];

    float lg[KK];
#pragma unroll
    for (int kk = 0; kk < KK; kk++) {
        const float* mk = mem_bank + (((size_t)b*MM + idxs[kk])*2 + 0)*Dd + h*HDd;
        float d = q0 * mk[lane] + q1 * mk[lane + 32];
#pragma unroll
        for (int o = 16; o; o >>= 1) d += __shfl_xor_sync(0xffffffffu, d, o);
        lg[kk] = d * SCALE;
    }

    float mx = fmaxf(lg[0], fmaxf(lg[1], lg[2]));
    float e0 = __expf(lg[0]-mx), e1 = __expf(lg[1]-mx), e2 = __expf(lg[2]-mx);
    float inv = 1.0f / (e0 + e1 + e2);
    e0 *= inv; e1 *= inv; e2 *= inv;

    const float* mv0 = mem_bank + (((size_t)b*MM + idxs[0])*2 + 1)*Dd + h*HDd;
    const float* mv1 = mem_bank + (((size_t)b*MM + idxs[1])*2 + 1)*Dd + h*HDd;
    const float* mv2 = mem_bank + (((size_t)b*MM + idxs[2])*2 + 1)*Dd + h*HDd;

    float o0 = e0*mv0[lane]      + e1*mv1[lane]      + e2*mv2[lane];
    float o1 = e0*mv0[lane + 32] + e1*mv1[lane + 32] + e2*mv2[lane + 32];

    float g = gate_bias[h];
    const float* arow = g_att + (size_t)bt*Dd + h*HDd;
    float c0 = o0*g + arow[lane]      * (1.0f - g);
    float c1 = o1*g + arow[lane + 32] * (1.0f - g);

    float* crow = g_comb + (size_t)bt*Dd + h*HDd;
    crow[lane]      = __bfloat162float(__float2bfloat16(c0));
    crow[lane + 32] = __bfloat162float(__float2bfloat16(c1));
}

// ---------------- launch ----------------
extern "C" void kernel_launch(void* const* d_in, const int* in_sizes, int n_in,
                              void* d_out, int out_size)
{
    (void)in_sizes; (void)n_in; (void)out_size;
    const float* x    = (const float*)d_in[0];
    const float* Wq   = (const float*)d_in[1];
    const float* bq   = (const float*)d_in[2];
    const float* Wk   = (const float*)d_in[3];
    const float* bk   = (const float*)d_in[4];
    const float* Wv   = (const float*)d_in[5];
    const float* bv   = (const float*)d_in[6];
    const float* Wo   = (const float*)d_in[7];
    const float* bo   = (const float*)d_in[8];
    const float* gate = (const float*)d_in[9];
    const float* memb = (const float*)d_in[10];
    const int*   knn  = (const int*)d_in[11];
    float* out = (float*)d_out;

    const int Mrows = Bb * Tt;           // 4096

    // launch 0: all tf32 splits fused (x + 4 weight matrices)
    split_all_kernel<<<dim3(1024, 1, 5), 256>>>(x, Wq, Wk, Wv, Wo);

    cudaFuncSetAttribute(gemm_qkv_kernel,
                         cudaFuncAttributeMaxDynamicSharedMemorySize, GEMM_SMEM);
    cudaFuncSetAttribute(gemm_o_kernel,
                         cudaFuncAttributeMaxDynamicSharedMemorySize, GEMM_SMEM);

    // launch 1
    gemm_qkv_kernel<<<dim3(Dd/128, Mrows/128, 3), 256, GEMM_SMEM>>>(bq, bk, bv);

    // launch 2
    l2norm_kernel<<<dim3(Mrows, 2), 256>>>();

    // launch 3  (ncu capture index -> flash profile next round)
    cudaFuncSetAttribute(flash_mma_kernel,
                         cudaFuncAttributeMaxDynamicSharedMemorySize, FLASH_SMEM);
    flash_mma_kernel<<<dim3(Tt/64, Bb*Hh), 128, FLASH_SMEM>>>();

    // launch 4
    mem_combine_kernel<<<Mrows, 512>>>(memb, knn, gate);

    // launch 5
    gemm_o_kernel<<<dim3(Dd/128, Mrows/128, 1), 256, GEMM_SMEM>>>(bo, out);
}

// round 16
// speedup vs baseline: 1.5413x; 1.5116x over previous
#include <cuda_runtime.h>
#include <cuda_bf16.h>
#include <math.h>
#include <stdint.h>

#define Bb   2
#define Tt   2048
#define Dd   1024
#define Hh   16
#define HDd  64
#define KK   3
#define MM   16384
#define SCALE 4096.0f

// ---------------- scratch (no cudaMalloc allowed) ----------------
__device__ float g_q[Bb*Tt*Dd];
__device__ float g_k[Bb*Tt*Dd];
__device__ float g_v[Bb*Tt*Dd];
__device__ float g_att[Bb*Tt*Dd];
__device__ float g_comb[Bb*Tt*Dd];

// tf32 split scratch
__device__ float g_xhi[Bb*Tt*Dd];
__device__ float g_xlo[Bb*Tt*Dd];
__device__ float g_whi[3*Dd*Dd];
__device__ float g_wlo[3*Dd*Dd];
__device__ float g_wohi[Dd*Dd];
__device__ float g_wolo[Dd*Dd];

// ================= helpers =================
__device__ __forceinline__ void split2(float v, float& hi, float& lo) {
    hi = __uint_as_float(__float_as_uint(v) & 0xFFFFE000u);
    lo = v - hi;
}
__device__ __forceinline__ float ex2(float x) {
    float y;
    asm("ex2.approx.ftz.f32 %0, %1;" : "=f"(y) : "f"(x));
    return y;
}
__device__ __forceinline__ uint32_t smem_u32(const void* p) {
    uint32_t a;
    asm("{ .reg .u64 t; cvta.to.shared.u64 t, %1; cvt.u32.u64 %0, t; }"
        : "=r"(a) : "l"(p));
    return a;
}
__device__ __forceinline__ void cp_async16(uint32_t dst, const void* src) {
    asm volatile("cp.async.ca.shared.global [%0], [%1], 16;" :: "r"(dst), "l"(src));
}
__device__ __forceinline__ void cp_commit() {
    asm volatile("cp.async.commit_group;");
}
template<int N>
__device__ __forceinline__ void cp_wait() {
    asm volatile("cp.async.wait_group %0;" :: "n"(N));
}

// ================= split kernels =================
// z=0 -> x, z=1..3 -> Wq, Wk, Wv
__global__ __launch_bounds__(256)
void split4_kernel(const float* __restrict__ x,
                   const float* __restrict__ Wq, const float* __restrict__ Wk,
                   const float* __restrict__ Wv)
{
    const int z = blockIdx.z;
    const float* src;
    float *hi, *lo;
    int n4;
    if (z == 0) {
        src = x;  hi = g_xhi;  lo = g_xlo;  n4 = Bb*Tt*Dd/4;
    } else {
        src = (z == 1) ? Wq : (z == 2) ? Wk : Wv;
        hi  = g_whi + (size_t)(z-1) * Dd * Dd;
        lo  = g_wlo + (size_t)(z-1) * Dd * Dd;
        n4  = Dd*Dd/4;
    }
    int i = blockIdx.x * blockDim.x + threadIdx.x;
    for (; i < n4; i += gridDim.x * blockDim.x) {
        float4 v = ((const float4*)src)[i];
        float4 h, l;
        split2(v.x, h.x, l.x);
        split2(v.y, h.y, l.y);
        split2(v.z, h.z, l.z);
        split2(v.w, h.w, l.w);
        ((float4*)hi)[i] = h;
        ((float4*)lo)[i] = l;
    }
}

__global__ __launch_bounds__(256)
void split_tf32_kernel(const float* __restrict__ a, float* __restrict__ hi,
                       float* __restrict__ lo, int n4)
{
    int i = blockIdx.x * blockDim.x + threadIdx.x;
    for (; i < n4; i += gridDim.x * blockDim.x) {
        float4 v = ((const float4*)a)[i];
        float4 h, l;
        split2(v.x, h.x, l.x);
        split2(v.y, h.y, l.y);
        split2(v.z, h.z, l.z);
        split2(v.w, h.w, l.w);
        ((float4*)hi)[i] = h;
        ((float4*)lo)[i] = l;
    }
}

// ================= mma.sync m16n8k8 tf32 =================
__device__ __forceinline__ void mma_16n8k8(float* d, const uint32_t* a, const uint32_t* b)
{
    asm volatile(
        "mma.sync.aligned.m16n8k8.row.col.f32.tf32.tf32.f32 "
        "{%0,%1,%2,%3}, {%4,%5,%6,%7}, {%8,%9}, {%0,%1,%2,%3};"
        : "+f"(d[0]), "+f"(d[1]), "+f"(d[2]), "+f"(d[3])
        : "r"(a[0]), "r"(a[1]), "r"(a[2]), "r"(a[3]), "r"(b[0]), "r"(b[1]));
}

// ==== tf32x3 GEMM tile (128x128, K=1024, BK=16, 2-stage cp.async) ====
#define TS2    20
#define BUF2   (128*TS2)
#define STAGE2 (4*BUF2)
#define GEMM_SMEM (2*STAGE2*4)    // 81920 B

__device__ __forceinline__ void gemm_tile_mma(
    const float* __restrict__ Ahi, const float* __restrict__ Alo,
    const float* __restrict__ Bhi, const float* __restrict__ Blo,
    const float* __restrict__ bias, float* __restrict__ C, int use_alo)
{
    extern __shared__ float sm[];
    const uint32_t sbase = smem_u32(sm);

    const int tid  = threadIdx.x;
    const int lane = tid & 31;
    const int wid  = tid >> 5;
    const int warp_m = wid >> 2;
    const int warp_n = wid & 3;
    const int m0 = blockIdx.y * 128;
    const int n0 = blockIdx.x * 128;

    float acc[4][4][4];
#pragma unroll
    for (int i = 0; i < 4; i++)
#pragma unroll
        for (int j = 0; j < 4; j++)
#pragma unroll
            for (int c = 0; c < 4; c++) acc[i][j][c] = 0.0f;

    const int lr = tid >> 1;
    const int ch = (tid & 1) * 8;

    auto stage_load = [&](int k0, int s) {
        uint32_t dst = sbase + (uint32_t)(s * STAGE2 + lr * TS2 + ch) * 4;
        const float* gAh = Ahi + (size_t)(m0 + lr) * Dd + k0 + ch;
        const float* gBh = Bhi + (size_t)(n0 + lr) * Dd + k0 + ch;
        const float* gBl = Blo + (size_t)(n0 + lr) * Dd + k0 + ch;
        cp_async16(dst,                 gAh);
        cp_async16(dst + 16,            gAh + 4);
        cp_async16(dst + 2*BUF2*4,      gBh);
        cp_async16(dst + 2*BUF2*4 + 16, gBh + 4);
        cp_async16(dst + 3*BUF2*4,      gBl);
        cp_async16(dst + 3*BUF2*4 + 16, gBl + 4);
        if (use_alo) {
            const float* gAl = Alo + (size_t)(m0 + lr) * Dd + k0 + ch;
            cp_async16(dst + BUF2*4,      gAl);
            cp_async16(dst + BUF2*4 + 16, gAl + 4);
        }
    };

    stage_load(0, 0);
    cp_commit();

    const int fr = warp_m * 64 + (lane >> 2);
    const int fn = warp_n * 32 + (lane >> 2);
    const int NIT = Dd / 16;

    for (int it = 0; it < NIT; it++) {
        const int s = it & 1;
        __syncthreads();
        if (it + 1 < NIT) {
            stage_load((it + 1) * 16, s ^ 1);
            cp_commit();
            cp_wait<1>();
        } else {
            cp_wait<0>();
        }
        __syncthreads();

        const uint32_t* uAh = (const uint32_t*)(sm + s*STAGE2);
        const uint32_t* uAl = uAh + BUF2;
        const uint32_t* uBh = uAh + 2*BUF2;
        const uint32_t* uBl = uAh + 3*BUF2;

#pragma unroll
        for (int kc = 0; kc < 2; kc++) {
            const int c0 = kc * 8 + (lane & 3);
            uint32_t af[4][4], bh[4][2], bl[4][2];
#pragma unroll
            for (int mr = 0; mr < 4; mr++) {
                int base = (fr + mr*16) * TS2 + c0;
                af[mr][0] = uAh[base];
                af[mr][1] = uAh[base + 8*TS2];
                af[mr][2] = uAh[base + 4];
                af[mr][3] = uAh[base + 8*TS2 + 4];
            }
#pragma unroll
            for (int nc = 0; nc < 4; nc++) {
                int base = (fn + nc*8) * TS2 + c0;
                bh[nc][0] = uBh[base];
                bh[nc][1] = uBh[base + 4];
                bl[nc][0] = uBl[base];
                bl[nc][1] = uBl[base + 4];
            }
#pragma unroll
            for (int mr = 0; mr < 4; mr++)
#pragma unroll
                for (int nc = 0; nc < 4; nc++)
                    mma_16n8k8(acc[mr][nc], af[mr], bh[nc]);
#pragma unroll
            for (int mr = 0; mr < 4; mr++)
#pragma unroll
                for (int nc = 0; nc < 4; nc++)
                    mma_16n8k8(acc[mr][nc], af[mr], bl[nc]);
            if (use_alo) {
#pragma unroll
                for (int mr = 0; mr < 4; mr++) {
                    int base = (fr + mr*16) * TS2 + c0;
                    af[mr][0] = uAl[base];
                    af[mr][1] = uAl[base + 8*TS2];
                    af[mr][2] = uAl[base + 4];
                    af[mr][3] = uAl[base + 8*TS2 + 4];
                }
#pragma unroll
                for (int mr = 0; mr < 4; mr++)
#pragma unroll
                    for (int nc = 0; nc < 4; nc++)
                        mma_16n8k8(acc[mr][nc], af[mr], bh[nc]);
            }
        }
    }

#pragma unroll
    for (int mr = 0; mr < 4; mr++) {
        int row = m0 + warp_m*64 + mr*16 + (lane >> 2);
#pragma unroll
        for (int nc = 0; nc < 4; nc++) {
            int col = n0 + warp_n*32 + nc*8 + (lane & 3)*2;
            float b0 = bias[col], b1 = bias[col+1];
            float2 v0 = make_float2(acc[mr][nc][0] + b0, acc[mr][nc][1] + b1);
            float2 v1 = make_float2(acc[mr][nc][2] + b0, acc[mr][nc][3] + b1);
            *(float2*)(C + (size_t)row * Dd + col)       = v0;
            *(float2*)(C + (size_t)(row+8) * Dd + col)   = v1;
        }
    }
}

__global__ __launch_bounds__(256, 2)
void gemm_qkv_kernel(const float* __restrict__ bq, const float* __restrict__ bk,
                     const float* __restrict__ bv)
{
    const int z = blockIdx.z;
    const float* Bhi = g_whi + (size_t)z * Dd * Dd;
    const float* Blo = g_wlo + (size_t)z * Dd * Dd;
    const float* bias = (z == 0) ? bq : (z == 1) ? bk : bv;
    float* C = (z == 0) ? g_q : (z == 1) ? g_k : g_v;
    gemm_tile_mma(g_xhi, g_xlo, Bhi, Blo, bias, C, 1);
}

__global__ __launch_bounds__(256, 2)
void gemm_o_kernel(const float* __restrict__ bo, float* __restrict__ out)
{
    gemm_tile_mma(g_comb, g_comb, g_wohi, g_wolo, bo, out, 0);
}

// ---------------- row-wise L2 normalization of g_q / g_k ----------------
__global__ __launch_bounds__(256)
void l2norm_kernel()
{
    float* buf = (blockIdx.y == 0) ? g_q : g_k;
    float* row = buf + (size_t)blockIdx.x * Dd;
    const int tid = threadIdx.x;

    float4 v = *(float4*)(row + tid * 4);
    float s = v.x*v.x + v.y*v.y + v.z*v.z + v.w*v.w;
#pragma unroll
    for (int o = 16; o; o >>= 1) s += __shfl_xor_sync(0xffffffffu, s, o);

    __shared__ float ws[8];
    if ((tid & 31) == 0) ws[tid >> 5] = s;
    __syncthreads();
    float tot = 0.0f;
#pragma unroll
    for (int w = 0; w < 8; w++) tot += ws[w];

    float r = 1.0f / fmaxf(sqrtf(tot), 1e-12f);
    v.x *= r; v.y *= r; v.z *= r; v.w *= r;
    *(float4*)(row + tid * 4) = v;
}

// ============ tensor-core causal flash attention v7 (tf32x3) ============
// BM=64 (4 warps x 16 rows), BN=64, 128 threads, 2 CTAs/SM.
// Cross-tile software pipeline: QK(jt+1) issued BEFORE softmax(jt) so the
// tensor pipe drains the burst while the warp does softmax ALU; Sn isn't read
// until next iteration. Triple-buffered K/V via cp.async.
// Per-accumulator fp op order identical to v3 -> bit-identical results.
#define FKS 68
#define FVS 72
#define FBUF (64*FKS + 64*FVS)          // 8960 floats
#define FLASH_SMEM (3*FBUF*4)           // 107520 B

__global__ __launch_bounds__(128, 2)
void flash_mma_kernel()
{
    extern __shared__ float fsm[];
    const uint32_t sbase = smem_u32(fsm);

    const int qt = (int)(gridDim.x - 1) - (int)blockIdx.x;  // big tiles first
    const int b  = blockIdx.y >> 4;
    const int h  = blockIdx.y & 15;
    const int q0 = qt * 64;
    const int tid  = threadIdx.x;
    const int lane = tid & 31;
    const int wid  = tid >> 5;
    const int row  = lane >> 2;
    const int qr   = lane & 3;
    const int r0g  = q0 + wid*16 + row;
    const int r1g  = r0g + 8;

    const size_t kvbase = (size_t)b*Tt*Dd + h*HDd;

    // ---- Q fragments into registers (log2 domain, hi/lo split) ----
    const float qsc = SCALE * 1.4426950408889634f;
    uint32_t qh[8][4], ql[8][4];
    {
        const float* q0p = g_q + kvbase + (size_t)r0g*Dd;
        const float* q1p = g_q + kvbase + (size_t)r1g*Dd;
#pragma unroll
        for (int kc = 0; kc < 8; kc++) {
            int c = kc*8 + qr;
            float a0 = q0p[c]   * qsc;
            float a1 = q1p[c]   * qsc;
            float a2 = q0p[c+4] * qsc;
            float a3 = q1p[c+4] * qsc;
            float hh, ll;
            split2(a0, hh, ll); qh[kc][0] = __float_as_uint(hh); ql[kc][0] = __float_as_uint(ll);
            split2(a1, hh, ll); qh[kc][1] = __float_as_uint(hh); ql[kc][1] = __float_as_uint(ll);
            split2(a2, hh, ll); qh[kc][2] = __float_as_uint(hh); ql[kc][2] = __float_as_uint(ll);
            split2(a3, hh, ll); qh[kc][3] = __float_as_uint(hh); ql[kc][3] = __float_as_uint(ll);
        }
    }

    float m0 = -INFINITY, m1 = -INFINITY, l0 = 0.0f, l1 = 0.0f;
    float O[8][4];
#pragma unroll
    for (int na = 0; na < 8; na++)
#pragma unroll
        for (int c = 0; c < 4; c++) O[na][c] = 0.0f;

    auto stage = [&](int jt) {
        const int buf = jt % 3;
        const float* gK = g_k + kvbase + (size_t)jt*64*Dd;
        const float* gV = g_v + kvbase + (size_t)jt*64*Dd;
        uint32_t dK = sbase + (uint32_t)buf * (FBUF*4);
        uint32_t dV = dK + 64*FKS*4;
        for (int i = tid; i < 1024; i += 128) {
            int r  = i >> 4;
            int f4 = (i & 15) * 4;
            cp_async16(dK + (r*FKS + f4)*4, gK + (size_t)r*Dd + f4);
            cp_async16(dV + (r*FVS + f4)*4, gV + (size_t)r*Dd + f4);
        }
    };

    // QK of tile jt (buffer jt%3) accumulated into S (split K on load)
    auto qk_tile = [&](float (*S)[4], const float* sK) {
#pragma unroll
        for (int kc = 0; kc < 8; kc++) {
#pragma unroll
            for (int na = 0; na < 8; na++) {
                int bb = (na*8 + row)*FKS + kc*8 + qr;
                float h0, l0s, h1, l1s;
                split2(sK[bb],     h0, l0s);
                split2(sK[bb + 4], h1, l1s);
                uint32_t bh[2] = { __float_as_uint(h0),  __float_as_uint(h1)  };
                uint32_t bl[2] = { __float_as_uint(l0s), __float_as_uint(l1s) };
                mma_16n8k8(S[na], qh[kc], bh);
                mma_16n8k8(S[na], qh[kc], bl);
                mma_16n8k8(S[na], ql[kc], bh);
            }
        }
    };

    // ---- prologue: stage tiles 0 and 1, compute S = QK(0) ----
    stage(0);
    cp_commit();
    if (qt >= 1) {
        stage(1);
        cp_commit();
        cp_wait<1>();
    } else {
        cp_wait<0>();
    }
    __syncthreads();

    float S[8][4], Sn[8][4];
#pragma unroll
    for (int na = 0; na < 8; na++)
#pragma unroll
        for (int c = 0; c < 4; c++) S[na][c] = 0.0f;
    qk_tile(S, fsm + 0*FBUF);

    const int srcA0 = (lane & ~3) | (qr >> 1);
    const int srcB0 = srcA0 + 2;
    const bool odd = (qr & 1);

    for (int jt = 0; jt <= qt; jt++) {
        if (jt < qt) {
            // buffer rotation: prefetch jt+2, wait for jt+1
            __syncthreads();                        // all warps done with tile jt-1
            if (jt + 2 <= qt) {
                stage(jt + 2);
                cp_commit();
                cp_wait<1>();
            } else {
                cp_wait<0>();
            }
            __syncthreads();                        // tile jt+1 visible

            // ---- QK(jt+1) -> Sn, issued BEFORE softmax(jt) ----
#pragma unroll
            for (int na = 0; na < 8; na++)
#pragma unroll
                for (int c = 0; c < 4; c++) Sn[na][c] = 0.0f;
            qk_tile(Sn, fsm + ((jt + 1) % 3)*FBUF);
        }

        // ---- causal mask (diagonal tile) ----
        if (jt == qt) {
#pragma unroll
            for (int na = 0; na < 8; na++) {
                int c0 = jt*64 + na*8 + qr*2;
                if (c0     > r0g) S[na][0] = -INFINITY;
                if (c0 + 1 > r0g) S[na][1] = -INFINITY;
                if (c0     > r1g) S[na][2] = -INFINITY;
                if (c0 + 1 > r1g) S[na][3] = -INFINITY;
            }
        }

        // ---- online softmax (base-2) on tile jt ----
        float mx0 = -INFINITY, mx1 = -INFINITY;
#pragma unroll
        for (int na = 0; na < 8; na++) {
            mx0 = fmaxf(mx0, fmaxf(S[na][0], S[na][1]));
            mx1 = fmaxf(mx1, fmaxf(S[na][2], S[na][3]));
        }
        mx0 = fmaxf(mx0, __shfl_xor_sync(0xffffffffu, mx0, 1));
        mx0 = fmaxf(mx0, __shfl_xor_sync(0xffffffffu, mx0, 2));
        mx1 = fmaxf(mx1, __shfl_xor_sync(0xffffffffu, mx1, 1));
        mx1 = fmaxf(mx1, __shfl_xor_sync(0xffffffffu, mx1, 2));

        float mn0 = fmaxf(m0, mx0), mn1 = fmaxf(m1, mx1);
        float f0 = ex2(m0 - mn0),   f1 = ex2(m1 - mn1);
        m0 = mn0; m1 = mn1;
        l0 *= f0; l1 *= f1;
#pragma unroll
        for (int na = 0; na < 8; na++) {
            O[na][0] *= f0; O[na][1] *= f0;
            O[na][2] *= f1; O[na][3] *= f1;
        }

        float rs0 = 0.0f, rs1 = 0.0f;
#pragma unroll
        for (int na = 0; na < 8; na++) {
            float p0 = ex2(S[na][0] - mn0);
            float p1 = ex2(S[na][1] - mn0);
            float p2 = ex2(S[na][2] - mn1);
            float p3 = ex2(S[na][3] - mn1);
            S[na][0] = p0; S[na][1] = p1; S[na][2] = p2; S[na][3] = p3;
            rs0 += p0 + p1;
            rs1 += p2 + p3;
        }
        rs0 += __shfl_xor_sync(0xffffffffu, rs0, 1);
        rs0 += __shfl_xor_sync(0xffffffffu, rs0, 2);
        rs1 += __shfl_xor_sync(0xffffffffu, rs1, 1);
        rs1 += __shfl_xor_sync(0xffffffffu, rs1, 2);
        l0 += rs0; l1 += rs1;

        // ---- O += P V(jt) : P via in-warp shuffle, V split-on-load ----
        const float* sV = fsm + (jt % 3)*FBUF + 64*FKS;
#pragma unroll
        for (int kc = 0; kc < 8; kc++) {
            float h0v = __shfl_sync(0xffffffffu, S[kc][0], srcA0);
            float h1v = __shfl_sync(0xffffffffu, S[kc][1], srcA0);
            float g0v = __shfl_sync(0xffffffffu, S[kc][0], srcB0);
            float g1v = __shfl_sync(0xffffffffu, S[kc][1], srcB0);
            float h2v = __shfl_sync(0xffffffffu, S[kc][2], srcA0);
            float h3v = __shfl_sync(0xffffffffu, S[kc][3], srcA0);
            float g2v = __shfl_sync(0xffffffffu, S[kc][2], srcB0);
            float g3v = __shfl_sync(0xffffffffu, S[kc][3], srcB0);
            float a0 = odd ? h1v : h0v;
            float a1 = odd ? h3v : h2v;
            float a2 = odd ? g1v : g0v;
            float a3 = odd ? g3v : g2v;
            float hh, ll;
            uint32_t ph[4], pl[4];
            split2(a0, hh, ll); ph[0] = __float_as_uint(hh); pl[0] = __float_as_uint(ll);
            split2(a1, hh, ll); ph[1] = __float_as_uint(hh); pl[1] = __float_as_uint(ll);
            split2(a2, hh, ll); ph[2] = __float_as_uint(hh); pl[2] = __float_as_uint(ll);
            split2(a3, hh, ll); ph[3] = __float_as_uint(hh); pl[3] = __float_as_uint(ll);

            int vb0 = (kc*8 + qr)*FVS + row;
#pragma unroll
            for (int na = 0; na < 8; na++) {
                float v0 = sV[vb0 + na*8];
                float v1 = sV[vb0 + 4*FVS + na*8];
                float vh0, vl0, vh1, vl1;
                split2(v0, vh0, vl0);
                split2(v1, vh1, vl1);
                uint32_t vh[2] = { __float_as_uint(vh0), __float_as_uint(vh1) };
                uint32_t vl[2] = { __float_as_uint(vl0), __float_as_uint(vl1) };
                mma_16n8k8(O[na], ph, vh);
                mma_16n8k8(O[na], ph, vl);
                mma_16n8k8(O[na], pl, vh);
            }
        }

        // rotate pipelined S
        if (jt < qt) {
#pragma unroll
            for (int na = 0; na < 8; na++)
#pragma unroll
                for (int c = 0; c < 4; c++) S[na][c] = Sn[na][c];
        }
    }

    // ---- epilogue ----
    float inv0 = 1.0f / l0, inv1 = 1.0f / l1;
#pragma unroll
    for (int na = 0; na < 8; na++) {
        int d = na*8 + qr*2;
        *(float2*)&g_att[(size_t)b*Tt*Dd + (size_t)r0g*Dd + h*HDd + d] =
            make_float2(O[na][0]*inv0, O[na][1]*inv0);
        *(float2*)&g_att[(size_t)b*Tt*Dd + (size_t)r1g*Dd + h*HDd + d] =
            make_float2(O[na][2]*inv1, O[na][3]*inv1);
    }
}

// ---------------- KNN memory attention + gate + bf16 round ----------------
__global__ __launch_bounds__(512)
void mem_combine_kernel(const float* __restrict__ mem_bank,
                        const int*   __restrict__ knn_idx,
                        const float* __restrict__ gate_bias)
{
    const int bt = blockIdx.x;
    const int b  = bt / Tt;
    const int h  = threadIdx.x >> 5;
    const int lane = threadIdx.x & 31;

    int idxs[KK];
#pragma unroll
    for (int kk = 0; kk < KK; kk++) idxs[kk] = knn_idx[bt*KK + kk];

    const float* qrow = g_q + (size_t)bt*Dd + h*HDd;
    float q0 = qrow[lane], q1 = qrow[lane + 32];

    float lg[KK];
#pragma unroll
    for (int kk = 0; kk < KK; kk++) {
        const float* mk = mem_bank + (((size_t)b*MM + idxs[kk])*2 + 0)*Dd + h*HDd;
        float d = q0 * mk[lane] + q1 * mk[lane + 32];
#pragma unroll
        for (int o = 16; o; o >>= 1) d += __shfl_xor_sync(0xffffffffu, d, o);
        lg[kk] = d * SCALE;
    }

    float mx = fmaxf(lg[0], fmaxf(lg[1], lg[2]));
    float e0 = __expf(lg[0]-mx), e1 = __expf(lg[1]-mx), e2 = __expf(lg[2]-mx);
    float inv = 1.0f / (e0 + e1 + e2);
    e0 *= inv; e1 *= inv; e2 *= inv;

    const float* mv0 = mem_bank + (((size_t)b*MM + idxs[0])*2 + 1)*Dd + h*HDd;
    const float* mv1 = mem_bank + (((size_t)b*MM + idxs[1])*2 + 1)*Dd + h*HDd;
    const float* mv2 = mem_bank + (((size_t)b*MM + idxs[2])*2 + 1)*Dd + h*HDd;

    float o0 = e0*mv0[lane]      + e1*mv1[lane]      + e2*mv2[lane];
    float o1 = e0*mv0[lane + 32] + e1*mv1[lane + 32] + e2*mv2[lane + 32];

    float g = gate_bias[h];
    const float* arow = g_att + (size_t)bt*Dd + h*HDd;
    float c0 = o0*g + arow[lane]      * (1.0f - g);
    float c1 = o1*g + arow[lane + 32] * (1.0f - g);

    float* crow = g_comb + (size_t)bt*Dd + h*HDd;
    crow[lane]      = __bfloat162float(__float2bfloat16(c0));
    crow[lane + 32] = __bfloat162float(__float2bfloat16(c1));
}

// ---------------- launch ----------------
extern "C" void kernel_launch(void* const* d_in, const int* in_sizes, int n_in,
                              void* d_out, int out_size)
{
    (void)in_sizes; (void)n_in; (void)out_size;
    const float* x    = (const float*)d_in[0];
    const float* Wq   = (const float*)d_in[1];
    const float* bq   = (const float*)d_in[2];
    const float* Wk   = (const float*)d_in[3];
    const float* bk   = (const float*)d_in[4];
    const float* Wv   = (const float*)d_in[5];
    const float* bv   = (const float*)d_in[6];
    const float* Wo   = (const float*)d_in[7];
    const float* bo   = (const float*)d_in[8];
    const float* gate = (const float*)d_in[9];
    const float* memb = (const float*)d_in[10];
    const int*   knn  = (const int*)d_in[11];
    float* out = (float*)d_out;

    float *wohi, *wolo;
    cudaGetSymbolAddress((void**)&wohi, g_wohi);
    cudaGetSymbolAddress((void**)&wolo, g_wolo);

    const int Mrows = Bb * Tt;           // 4096

    // launch 0: split x + Wq/Wk/Wv (Wo split deferred until after flash)
    split4_kernel<<<dim3(1024, 1, 4), 256>>>(x, Wq, Wk, Wv);

    cudaFuncSetAttribute(gemm_qkv_kernel,
                         cudaFuncAttributeMaxDynamicSharedMemorySize, GEMM_SMEM);
    cudaFuncSetAttribute(gemm_o_kernel,
                         cudaFuncAttributeMaxDynamicSharedMemorySize, GEMM_SMEM);

    // launch 1
    gemm_qkv_kernel<<<dim3(Dd/128, Mrows/128, 3), 256, GEMM_SMEM>>>(bq, bk, bv);

    // launch 2
    l2norm_kernel<<<dim3(Mrows, 2), 256>>>();

    // launch 3  (ncu capture index -> flash profile)
    cudaFuncSetAttribute(flash_mma_kernel,
                         cudaFuncAttributeMaxDynamicSharedMemorySize, FLASH_SMEM);
    flash_mma_kernel<<<dim3(Tt/64, Bb*Hh), 128, FLASH_SMEM>>>();

    // launch 4
    mem_combine_kernel<<<Mrows, 512>>>(memb, knn, gate);

    // launch 5: Wo split (only needed by gemm_o)
    split_tf32_kernel<<<1024, 256>>>(Wo, wohi, wolo, Dd*Dd/4);

    // launch 6
    gemm_o_kernel<<<dim3(Dd/128, Mrows/128, 1), 256, GEMM_SMEM>>>(bo, out);
}

// round 17
// speedup vs baseline: 1.6904x; 1.0968x over previous
#include <cuda_runtime.h>
#include <cuda_bf16.h>
#include <math.h>
#include <stdint.h>

#define Bb   2
#define Tt   2048
#define Dd   1024
#define Hh   16
#define HDd  64
#define KK   3
#define MM   16384
#define SCALE 4096.0f

// ---------------- scratch (no cudaMalloc allowed) ----------------
__device__ float g_q[Bb*Tt*Dd];
__device__ float g_k[Bb*Tt*Dd];
__device__ float g_v[Bb*Tt*Dd];
__device__ float g_att[Bb*Tt*Dd];
__device__ float g_comb[Bb*Tt*Dd];

// tf32 split scratch (weights only; activations split on load)
__device__ float g_whi[3*Dd*Dd];
__device__ float g_wlo[3*Dd*Dd];
__device__ float g_wohi[Dd*Dd];
__device__ float g_wolo[Dd*Dd];

// ================= helpers =================
__device__ __forceinline__ void split2(float v, float& hi, float& lo) {
    hi = __uint_as_float(__float_as_uint(v) & 0xFFFFE000u);
    lo = v - hi;
}
__device__ __forceinline__ float ex2(float x) {
    float y;
    asm("ex2.approx.ftz.f32 %0, %1;" : "=f"(y) : "f"(x));
    return y;
}
__device__ __forceinline__ uint32_t smem_u32(const void* p) {
    uint32_t a;
    asm("{ .reg .u64 t; cvta.to.shared.u64 t, %1; cvt.u32.u64 %0, t; }"
        : "=r"(a) : "l"(p));
    return a;
}
__device__ __forceinline__ void cp_async16(uint32_t dst, const void* src) {
    asm volatile("cp.async.ca.shared.global [%0], [%1], 16;" :: "r"(dst), "l"(src));
}
__device__ __forceinline__ void cp_commit() {
    asm volatile("cp.async.commit_group;");
}
template<int N>
__device__ __forceinline__ void cp_wait() {
    asm volatile("cp.async.wait_group %0;" :: "n"(N));
}

// ================= weight split kernel: z=0..3 -> Wq, Wk, Wv, Wo =========
__global__ __launch_bounds__(256)
void split_w_kernel(const float* __restrict__ Wq, const float* __restrict__ Wk,
                    const float* __restrict__ Wv, const float* __restrict__ Wo)
{
    const int z = blockIdx.z;
    const float* src = (z == 0) ? Wq : (z == 1) ? Wk : (z == 2) ? Wv : Wo;
    float* hi = (z < 3) ? (g_whi + (size_t)z * Dd * Dd) : g_wohi;
    float* lo = (z < 3) ? (g_wlo + (size_t)z * Dd * Dd) : g_wolo;
    const int n4 = Dd * Dd / 4;
    int i = blockIdx.x * blockDim.x + threadIdx.x;
    for (; i < n4; i += gridDim.x * blockDim.x) {
        float4 v = ((const float4*)src)[i];
        float4 h, l;
        split2(v.x, h.x, l.x);
        split2(v.y, h.y, l.y);
        split2(v.z, h.z, l.z);
        split2(v.w, h.w, l.w);
        ((float4*)hi)[i] = h;
        ((float4*)lo)[i] = l;
    }
}

// ================= mma.sync m16n8k8 tf32 =================
__device__ __forceinline__ void mma_16n8k8(float* d, const uint32_t* a, const uint32_t* b)
{
    asm volatile(
        "mma.sync.aligned.m16n8k8.row.col.f32.tf32.tf32.f32 "
        "{%0,%1,%2,%3}, {%4,%5,%6,%7}, {%8,%9}, {%0,%1,%2,%3};"
        : "+f"(d[0]), "+f"(d[1]), "+f"(d[2]), "+f"(d[3])
        : "r"(a[0]), "r"(a[1]), "r"(a[2]), "r"(a[3]), "r"(b[0]), "r"(b[1]));
}

// ==== tf32x3 GEMM tile (128x128, K=1024, BK=16, 2-stage cp.async) ====
// A staged RAW (hi/lo derived on fragment load -> bit-identical values),
// B staged pre-split. Accumulation order per acc: k asc, hh->hl->lh per kc.
#define TS2    20
#define BUF2   (128*TS2)          // 2560 floats per array
#define STAGE3 (3*BUF2)           // 7680 floats per stage (Araw, Bhi, Blo)
#define GEMM_SMEM (2*STAGE3*4)    // 61440 B

__device__ __forceinline__ void gemm_tile_mma(
    const float* __restrict__ A,
    const float* __restrict__ Bhi, const float* __restrict__ Blo,
    const float* __restrict__ bias, float* __restrict__ C, int use_alo)
{
    extern __shared__ float sm[];
    const uint32_t sbase = smem_u32(sm);

    const int tid  = threadIdx.x;
    const int lane = tid & 31;
    const int wid  = tid >> 5;
    const int warp_m = wid >> 2;
    const int warp_n = wid & 3;
    const int m0 = blockIdx.y * 128;
    const int n0 = blockIdx.x * 128;

    float acc[4][4][4];
#pragma unroll
    for (int i = 0; i < 4; i++)
#pragma unroll
        for (int j = 0; j < 4; j++)
#pragma unroll
            for (int c = 0; c < 4; c++) acc[i][j][c] = 0.0f;

    const int lr = tid >> 1;          // 0..127 row within tile
    const int ch = (tid & 1) * 8;     // float offset 0 or 8

    auto stage_load = [&](int k0, int s) {
        uint32_t dst = sbase + (uint32_t)(s * STAGE3 + lr * TS2 + ch) * 4;
        const float* gA  = A   + (size_t)(m0 + lr) * Dd + k0 + ch;
        const float* gBh = Bhi + (size_t)(n0 + lr) * Dd + k0 + ch;
        const float* gBl = Blo + (size_t)(n0 + lr) * Dd + k0 + ch;
        cp_async16(dst,               gA);
        cp_async16(dst + 16,          gA + 4);
        cp_async16(dst + BUF2*4,      gBh);
        cp_async16(dst + BUF2*4 + 16, gBh + 4);
        cp_async16(dst + 2*BUF2*4,      gBl);
        cp_async16(dst + 2*BUF2*4 + 16, gBl + 4);
    };

    stage_load(0, 0);
    cp_commit();

    const int fr = warp_m * 64 + (lane >> 2);
    const int fn = warp_n * 32 + (lane >> 2);
    const int NIT = Dd / 16;          // 64

    for (int it = 0; it < NIT; it++) {
        const int s = it & 1;
        __syncthreads();
        if (it + 1 < NIT) {
            stage_load((it + 1) * 16, s ^ 1);
            cp_commit();
            cp_wait<1>();
        } else {
            cp_wait<0>();
        }
        __syncthreads();

        const uint32_t* uA  = (const uint32_t*)(sm + s*STAGE3);
        const uint32_t* uBh = uA + BUF2;
        const uint32_t* uBl = uA + 2*BUF2;

#pragma unroll
        for (int kc = 0; kc < 2; kc++) {
            const int c0 = kc * 8 + (lane & 3);
            uint32_t af[4][4], bh[4][2], bl[4][2];
            // A-hi fragments: load raw, mask to tf32-hi
#pragma unroll
            for (int mr = 0; mr < 4; mr++) {
                int base = (fr + mr*16) * TS2 + c0;
                af[mr][0] = uA[base]            & 0xFFFFE000u;
                af[mr][1] = uA[base + 8*TS2]    & 0xFFFFE000u;
                af[mr][2] = uA[base + 4]        & 0xFFFFE000u;
                af[mr][3] = uA[base + 8*TS2 + 4] & 0xFFFFE000u;
            }
#pragma unroll
            for (int nc = 0; nc < 4; nc++) {
                int base = (fn + nc*8) * TS2 + c0;
                bh[nc][0] = uBh[base];
                bh[nc][1] = uBh[base + 4];
                bl[nc][0] = uBl[base];
                bl[nc][1] = uBl[base + 4];
            }
#pragma unroll
            for (int mr = 0; mr < 4; mr++)
#pragma unroll
                for (int nc = 0; nc < 4; nc++)
                    mma_16n8k8(acc[mr][nc], af[mr], bh[nc]);
#pragma unroll
            for (int mr = 0; mr < 4; mr++)
#pragma unroll
                for (int nc = 0; nc < 4; nc++)
                    mma_16n8k8(acc[mr][nc], af[mr], bl[nc]);
            if (use_alo) {
                // A-lo fragments: reload raw, lo = raw - hi (bit-identical)
#pragma unroll
                for (int mr = 0; mr < 4; mr++) {
                    int base = (fr + mr*16) * TS2 + c0;
#pragma unroll
                    for (int j = 0; j < 4; j++) {
                        int o = (j & 1) ? base + 8*TS2 : base;
                        if (j >= 2) o += 4;
                        float f = __uint_as_float(uA[o]);
                        float h = __uint_as_float(uA[o] & 0xFFFFE000u);
                        af[mr][j] = __float_as_uint(f - h);
                    }
                }
#pragma unroll
                for (int mr = 0; mr < 4; mr++)
#pragma unroll
                    for (int nc = 0; nc < 4; nc++)
                        mma_16n8k8(acc[mr][nc], af[mr], bh[nc]);
            }
        }
    }

#pragma unroll
    for (int mr = 0; mr < 4; mr++) {
        int row = m0 + warp_m*64 + mr*16 + (lane >> 2);
#pragma unroll
        for (int nc = 0; nc < 4; nc++) {
            int col = n0 + warp_n*32 + nc*8 + (lane & 3)*2;
            float b0 = bias[col], b1 = bias[col+1];
            float2 v0 = make_float2(acc[mr][nc][0] + b0, acc[mr][nc][1] + b1);
            float2 v1 = make_float2(acc[mr][nc][2] + b0, acc[mr][nc][3] + b1);
            *(float2*)(C + (size_t)row * Dd + col)       = v0;
            *(float2*)(C + (size_t)(row+8) * Dd + col)   = v1;
        }
    }
}

__global__ __launch_bounds__(256, 2)
void gemm_qkv_kernel(const float* __restrict__ x,
                     const float* __restrict__ bq, const float* __restrict__ bk,
                     const float* __restrict__ bv)
{
    const int z = blockIdx.z;
    const float* Bhi = g_whi + (size_t)z * Dd * Dd;
    const float* Blo = g_wlo + (size_t)z * Dd * Dd;
    const float* bias = (z == 0) ? bq : (z == 1) ? bk : bv;
    float* C = (z == 0) ? g_q : (z == 1) ? g_k : g_v;
    gemm_tile_mma(x, Bhi, Blo, bias, C, 1);
}

__global__ __launch_bounds__(256, 2)
void gemm_o_kernel(const float* __restrict__ bo, float* __restrict__ out)
{
    // comb is bf16-rounded -> tf32-exact: hi == comb, lo == 0 -> 2 passes
    gemm_tile_mma(g_comb, g_wohi, g_wolo, bo, out, 0);
}

// ---------------- row-wise L2 normalization of g_q / g_k ----------------
__global__ __launch_bounds__(256)
void l2norm_kernel()
{
    float* buf = (blockIdx.y == 0) ? g_q : g_k;
    float* row = buf + (size_t)blockIdx.x * Dd;
    const int tid = threadIdx.x;

    float4 v = *(float4*)(row + tid * 4);
    float s = v.x*v.x + v.y*v.y + v.z*v.z + v.w*v.w;
#pragma unroll
    for (int o = 16; o; o >>= 1) s += __shfl_xor_sync(0xffffffffu, s, o);

    __shared__ float ws[8];
    if ((tid & 31) == 0) ws[tid >> 5] = s;
    __syncthreads();
    float tot = 0.0f;
#pragma unroll
    for (int w = 0; w < 8; w++) tot += ws[w];

    float r = 1.0f / fmaxf(sqrtf(tot), 1e-12f);
    v.x *= r; v.y *= r; v.z *= r; v.w *= r;
    *(float4*)(row + tid * 4) = v;
}

// ============ tensor-core causal flash attention v8 (tf32x3) ============
// v7 cross-tile pipeline (QK(jt+1) before softmax(jt), triple buffer) with
// Q stored RAW (32 regs, hi/lo derived per kc) to relieve register pressure.
#define FKS 68
#define FVS 72
#define FBUF (64*FKS + 64*FVS)          // 8960 floats
#define FLASH_SMEM (3*FBUF*4)           // 107520 B

__global__ __launch_bounds__(128, 2)
void flash_mma_kernel()
{
    extern __shared__ float fsm[];
    const uint32_t sbase = smem_u32(fsm);

    const int qt = (int)(gridDim.x - 1) - (int)blockIdx.x;  // big tiles first
    const int b  = blockIdx.y >> 4;
    const int h  = blockIdx.y & 15;
    const int q0 = qt * 64;
    const int tid  = threadIdx.x;
    const int lane = tid & 31;
    const int wid  = tid >> 5;
    const int row  = lane >> 2;
    const int qr   = lane & 3;
    const int r0g  = q0 + wid*16 + row;
    const int r1g  = r0g + 8;

    const size_t kvbase = (size_t)b*Tt*Dd + h*HDd;

    // ---- Q raw in registers, pre-scaled to log2 domain ----
    const float qsc = SCALE * 1.4426950408889634f;
    float qv[8][4];
    {
        const float* q0p = g_q + kvbase + (size_t)r0g*Dd;
        const float* q1p = g_q + kvbase + (size_t)r1g*Dd;
#pragma unroll
        for (int kc = 0; kc < 8; kc++) {
            int c = kc*8 + qr;
            qv[kc][0] = q0p[c]   * qsc;
            qv[kc][1] = q1p[c]   * qsc;
            qv[kc][2] = q0p[c+4] * qsc;
            qv[kc][3] = q1p[c+4] * qsc;
        }
    }

    float m0 = -INFINITY, m1 = -INFINITY, l0 = 0.0f, l1 = 0.0f;
    float O[8][4];
#pragma unroll
    for (int na = 0; na < 8; na++)
#pragma unroll
        for (int c = 0; c < 4; c++) O[na][c] = 0.0f;

    auto stage = [&](int jt) {
        const int buf = jt % 3;
        const float* gK = g_k + kvbase + (size_t)jt*64*Dd;
        const float* gV = g_v + kvbase + (size_t)jt*64*Dd;
        uint32_t dK = sbase + (uint32_t)buf * (FBUF*4);
        uint32_t dV = dK + 64*FKS*4;
        for (int i = tid; i < 1024; i += 128) {
            int r  = i >> 4;
            int f4 = (i & 15) * 4;
            cp_async16(dK + (r*FKS + f4)*4, gK + (size_t)r*Dd + f4);
            cp_async16(dV + (r*FVS + f4)*4, gV + (size_t)r*Dd + f4);
        }
    };

    // QK of one tile accumulated into S (Q and K split on use)
    auto qk_tile = [&](float (*S)[4], const float* sK) {
#pragma unroll
        for (int kc = 0; kc < 8; kc++) {
            uint32_t qhk[4], qlk[4];
#pragma unroll
            for (int c = 0; c < 4; c++) {
                float hh, ll;
                split2(qv[kc][c], hh, ll);
                qhk[c] = __float_as_uint(hh);
                qlk[c] = __float_as_uint(ll);
            }
#pragma unroll
            for (int na = 0; na < 8; na++) {
                int bb = (na*8 + row)*FKS + kc*8 + qr;
                float h0, l0s, h1, l1s;
                split2(sK[bb],     h0, l0s);
                split2(sK[bb + 4], h1, l1s);
                uint32_t bh[2] = { __float_as_uint(h0),  __float_as_uint(h1)  };
                uint32_t bl[2] = { __float_as_uint(l0s), __float_as_uint(l1s) };
                mma_16n8k8(S[na], qhk, bh);
                mma_16n8k8(S[na], qhk, bl);
                mma_16n8k8(S[na], qlk, bh);
            }
        }
    };

    // ---- prologue: stage tiles 0 and 1, compute S = QK(0) ----
    stage(0);
    cp_commit();
    if (qt >= 1) {
        stage(1);
        cp_commit();
        cp_wait<1>();
    } else {
        cp_wait<0>();
    }
    __syncthreads();

    float S[8][4], Sn[8][4];
#pragma unroll
    for (int na = 0; na < 8; na++)
#pragma unroll
        for (int c = 0; c < 4; c++) S[na][c] = 0.0f;
    qk_tile(S, fsm + 0*FBUF);

    const int srcA0 = (lane & ~3) | (qr >> 1);
    const int srcB0 = srcA0 + 2;
    const bool odd = (qr & 1);

    for (int jt = 0; jt <= qt; jt++) {
        if (jt < qt) {
            __syncthreads();                        // all warps done with tile jt-1
            if (jt + 2 <= qt) {
                stage(jt + 2);
                cp_commit();
                cp_wait<1>();
            } else {
                cp_wait<0>();
            }
            __syncthreads();                        // tile jt+1 visible

            // ---- QK(jt+1) -> Sn, issued BEFORE softmax(jt) ----
#pragma unroll
            for (int na = 0; na < 8; na++)
#pragma unroll
                for (int c = 0; c < 4; c++) Sn[na][c] = 0.0f;
            qk_tile(Sn, fsm + ((jt + 1) % 3)*FBUF);
        }

        // ---- causal mask (diagonal tile) ----
        if (jt == qt) {
#pragma unroll
            for (int na = 0; na < 8; na++) {
                int c0 = jt*64 + na*8 + qr*2;
                if (c0     > r0g) S[na][0] = -INFINITY;
                if (c0 + 1 > r0g) S[na][1] = -INFINITY;
                if (c0     > r1g) S[na][2] = -INFINITY;
                if (c0 + 1 > r1g) S[na][3] = -INFINITY;
            }
        }

        // ---- online softmax (base-2) on tile jt ----
        float mx0 = -INFINITY, mx1 = -INFINITY;
#pragma unroll
        for (int na = 0; na < 8; na++) {
            mx0 = fmaxf(mx0, fmaxf(S[na][0], S[na][1]));
            mx1 = fmaxf(mx1, fmaxf(S[na][2], S[na][3]));
        }
        mx0 = fmaxf(mx0, __shfl_xor_sync(0xffffffffu, mx0, 1));
        mx0 = fmaxf(mx0, __shfl_xor_sync(0xffffffffu, mx0, 2));
        mx1 = fmaxf(mx1, __shfl_xor_sync(0xffffffffu, mx1, 1));
        mx1 = fmaxf(mx1, __shfl_xor_sync(0xffffffffu, mx1, 2));

        float mn0 = fmaxf(m0, mx0), mn1 = fmaxf(m1, mx1);
        float f0 = ex2(m0 - mn0),   f1 = ex2(m1 - mn1);
        m0 = mn0; m1 = mn1;
        l0 *= f0; l1 *= f1;
#pragma unroll
        for (int na = 0; na < 8; na++) {
            O[na][0] *= f0; O[na][1] *= f0;
            O[na][2] *= f1; O[na][3] *= f1;
        }

        float rs0 = 0.0f, rs1 = 0.0f;
#pragma unroll
        for (int na = 0; na < 8; na++) {
            float p0 = ex2(S[na][0] - mn0);
            float p1 = ex2(S[na][1] - mn0);
            float p2 = ex2(S[na][2] - mn1);
            float p3 = ex2(S[na][3] - mn1);
            S[na][0] = p0; S[na][1] = p1; S[na][2] = p2; S[na][3] = p3;
            rs0 += p0 + p1;
            rs1 += p2 + p3;
        }
        rs0 += __shfl_xor_sync(0xffffffffu, rs0, 1);
        rs0 += __shfl_xor_sync(0xffffffffu, rs0, 2);
        rs1 += __shfl_xor_sync(0xffffffffu, rs1, 1);
        rs1 += __shfl_xor_sync(0xffffffffu, rs1, 2);
        l0 += rs0; l1 += rs1;

        // ---- O += P V(jt) : P via in-warp shuffle, V split-on-load ----
        const float* sV = fsm + (jt % 3)*FBUF + 64*FKS;
#pragma unroll
        for (int kc = 0; kc < 8; kc++) {
            float h0v = __shfl_sync(0xffffffffu, S[kc][0], srcA0);
            float h1v = __shfl_sync(0xffffffffu, S[kc][1], srcA0);
            float g0v = __shfl_sync(0xffffffffu, S[kc][0], srcB0);
            float g1v = __shfl_sync(0xffffffffu, S[kc][1], srcB0);
            float h2v = __shfl_sync(0xffffffffu, S[kc][2], srcA0);
            float h3v = __shfl_sync(0xffffffffu, S[kc][3], srcA0);
            float g2v = __shfl_sync(0xffffffffu, S[kc][2], srcB0);
            float g3v = __shfl_sync(0xffffffffu, S[kc][3], srcB0);
            float a0 = odd ? h1v : h0v;
            float a1 = odd ? h3v : h2v;
            float a2 = odd ? g1v : g0v;
            float a3 = odd ? g3v : g2v;
            float hh, ll;
            uint32_t ph[4], pl[4];
            split2(a0, hh, ll); ph[0] = __float_as_uint(hh); pl[0] = __float_as_uint(ll);
            split2(a1, hh, ll); ph[1] = __float_as_uint(hh); pl[1] = __float_as_uint(ll);
            split2(a2, hh, ll); ph[2] = __float_as_uint(hh); pl[2] = __float_as_uint(ll);
            split2(a3, hh, ll); ph[3] = __float_as_uint(hh); pl[3] = __float_as_uint(ll);

            int vb0 = (kc*8 + qr)*FVS + row;
#pragma unroll
            for (int na = 0; na < 8; na++) {
                float v0 = sV[vb0 + na*8];
                float v1 = sV[vb0 + 4*FVS + na*8];
                float vh0, vl0, vh1, vl1;
                split2(v0, vh0, vl0);
                split2(v1, vh1, vl1);
                uint32_t vh[2] = { __float_as_uint(vh0), __float_as_uint(vh1) };
                uint32_t vl[2] = { __float_as_uint(vl0), __float_as_uint(vl1) };
                mma_16n8k8(O[na], ph, vh);
                mma_16n8k8(O[na], ph, vl);
                mma_16n8k8(O[na], pl, vh);
            }
        }

        // rotate pipelined S
        if (jt < qt) {
#pragma unroll
            for (int na = 0; na < 8; na++)
#pragma unroll
                for (int c = 0; c < 4; c++) S[na][c] = Sn[na][c];
        }
    }

    // ---- epilogue ----
    float inv0 = 1.0f / l0, inv1 = 1.0f / l1;
#pragma unroll
    for (int na = 0; na < 8; na++) {
        int d = na*8 + qr*2;
        *(float2*)&g_att[(size_t)b*Tt*Dd + (size_t)r0g*Dd + h*HDd + d] =
            make_float2(O[na][0]*inv0, O[na][1]*inv0);
        *(float2*)&g_att[(size_t)b*Tt*Dd + (size_t)r1g*Dd + h*HDd + d] =
            make_float2(O[na][2]*inv1, O[na][3]*inv1);
    }
}

// ---------------- KNN memory attention + gate + bf16 round ----------------
__global__ __launch_bounds__(512)
void mem_combine_kernel(const float* __restrict__ mem_bank,
                        const int*   __restrict__ knn_idx,
                        const float* __restrict__ gate_bias)
{
    const int bt = blockIdx.x;
    const int b  = bt / Tt;
    const int h  = threadIdx.x >> 5;
    const int lane = threadIdx.x & 31;

    int idxs[KK];
#pragma unroll
    for (int kk = 0; kk < KK; kk++) idxs[kk] = knn_idx[bt*KK + kk];

    const float* qrow = g_q + (size_t)bt*Dd + h*HDd;
    float q0 = qrow[lane], q1 = qrow[lane + 32];

    float lg[KK];
#pragma unroll
    for (int kk = 0; kk < KK; kk++) {
        const float* mk = mem_bank + (((size_t)b*MM + idxs[kk])*2 + 0)*Dd + h*HDd;
        float d = q0 * mk[lane] + q1 * mk[lane + 32];
#pragma unroll
        for (int o = 16; o; o >>= 1) d += __shfl_xor_sync(0xffffffffu, d, o);
        lg[kk] = d * SCALE;
    }

    float mx = fmaxf(lg[0], fmaxf(lg[1], lg[2]));
    float e0 = __expf(lg[0]-mx), e1 = __expf(lg[1]-mx), e2 = __expf(lg[2]-mx);
    float inv = 1.0f / (e0 + e1 + e2);
    e0 *= inv; e1 *= inv; e2 *= inv;

    const float* mv0 = mem_bank + (((size_t)b*MM + idxs[0])*2 + 1)*Dd + h*HDd;
    const float* mv1 = mem_bank + (((size_t)b*MM + idxs[1])*2 + 1)*Dd + h*HDd;
    const float* mv2 = mem_bank + (((size_t)b*MM + idxs[2])*2 + 1)*Dd + h*HDd;

    float o0 = e0*mv0[lane]      + e1*mv1[lane]      + e2*mv2[lane];
    float o1 = e0*mv0[lane + 32] + e1*mv1[lane + 32] + e2*mv2[lane + 32];

    float g = gate_bias[h];
    const float* arow = g_att + (size_t)bt*Dd + h*HDd;
    float c0 = o0*g + arow[lane]      * (1.0f - g);
    float c1 = o1*g + arow[lane + 32] * (1.0f - g);

    float* crow = g_comb + (size_t)bt*Dd + h*HDd;
    crow[lane]      = __bfloat162float(__float2bfloat16(c0));
    crow[lane + 32] = __bfloat162float(__float2bfloat16(c1));
}

// ---------------- launch ----------------
extern "C" void kernel_launch(void* const* d_in, const int* in_sizes, int n_in,
                              void* d_out, int out_size)
{
    (void)in_sizes; (void)n_in; (void)out_size;
    const float* x    = (const float*)d_in[0];
    const float* Wq   = (const float*)d_in[1];
    const float* bq   = (const float*)d_in[2];
    const float* Wk   = (const float*)d_in[3];
    const float* bk   = (const float*)d_in[4];
    const float* Wv   = (const float*)d_in[5];
    const float* bv   = (const float*)d_in[6];
    const float* Wo   = (const float*)d_in[7];
    const float* bo   = (const float*)d_in[8];
    const float* gate = (const float*)d_in[9];
    const float* memb = (const float*)d_in[10];
    const int*   knn  = (const int*)d_in[11];
    float* out = (float*)d_out;

    const int Mrows = Bb * Tt;           // 4096

    // launch 0: split all 4 weight matrices (activations split on load)
    split_w_kernel<<<dim3(1024, 1, 4), 256>>>(Wq, Wk, Wv, Wo);

    cudaFuncSetAttribute(gemm_qkv_kernel,
                         cudaFuncAttributeMaxDynamicSharedMemorySize, GEMM_SMEM);
    cudaFuncSetAttribute(gemm_o_kernel,
                         cudaFuncAttributeMaxDynamicSharedMemorySize, GEMM_SMEM);

    // launch 1
    gemm_qkv_kernel<<<dim3(Dd/128, Mrows/128, 3), 256, GEMM_SMEM>>>(x, bq, bk, bv);

    // launch 2
    l2norm_kernel<<<dim3(Mrows, 2), 256>>>();

    // launch 3  (ncu capture index -> flash profile)
    cudaFuncSetAttribute(flash_mma_kernel,
                         cudaFuncAttributeMaxDynamicSharedMemorySize, FLASH_SMEM);
    flash_mma_kernel<<<dim3(Tt/64, Bb*Hh), 128, FLASH_SMEM>>>();

    // launch 4
    mem_combine_kernel<<<Mrows, 512>>>(memb, knn, gate);

    // launch 5
    gemm_o_kernel<<<dim3(Dd/128, Mrows/128, 1), 256, GEMM_SMEM>>>(bo, out);
}